// round 1
// baseline (speedup 1.0000x reference)
#include <cuda_runtime.h>
#include <cuda_bf16.h>
#include <math.h>

// ---------------- problem constants ----------------
#define SEQ      2048
#define DIM      2048
#define NHEADS   32
#define NKV      8
#define HDIM     64
#define KVDIM    (NKV * HDIM)      // 512

// ---------------- scratch (no allocs allowed) ----------------
__device__ float g_Q[(size_t)SEQ * DIM];     // 16 MB
__device__ float g_K[(size_t)SEQ * KVDIM];   // 4 MB
__device__ float g_V[(size_t)SEQ * KVDIM];   // 4 MB
__device__ float g_A[(size_t)SEQ * DIM];     // 16 MB (attention output, [s, h, d])

// ---------------- SGEMM: C[M,N] = A[M,K] @ B[K,N], fp32 ----------------
// 128x128 block tile, BK=8, 8x8 per-thread, 256 threads.
__global__ __launch_bounds__(256) void sgemm_kernel(
    int M, int N, int K,
    const float* __restrict__ A, const float* __restrict__ B,
    float* __restrict__ C)
{
    const int BM = 128, BN = 128, BK = 8, TM = 8, TN = 8;
    __shared__ float As[BK][BM];   // transposed A tile
    __shared__ float Bs[BK][BN];

    const int bx = blockIdx.x, by = blockIdx.y;
    const int tid = threadIdx.x;
    const int tRow = tid >> 4;      // 0..15
    const int tCol = tid & 15;      // 0..15

    const float* Ab = A + (size_t)by * BM * K;
    const float* Bb = B + (size_t)bx * BN;

    const int aRow = tid >> 1;          // 0..127
    const int aCol = (tid & 1) * 4;     // 0 or 4
    const int bRow = tid >> 5;          // 0..7
    const int bCol = (tid & 31) * 4;    // 0..124

    float acc[TM][TN];
    #pragma unroll
    for (int i = 0; i < TM; i++)
        #pragma unroll
        for (int j = 0; j < TN; j++) acc[i][j] = 0.0f;

    for (int k0 = 0; k0 < K; k0 += BK) {
        float4 av = *(const float4*)(Ab + (size_t)aRow * K + k0 + aCol);
        As[aCol + 0][aRow] = av.x;
        As[aCol + 1][aRow] = av.y;
        As[aCol + 2][aRow] = av.z;
        As[aCol + 3][aRow] = av.w;
        *(float4*)(&Bs[bRow][bCol]) =
            *(const float4*)(Bb + (size_t)(k0 + bRow) * N + bCol);
        __syncthreads();

        #pragma unroll
        for (int k = 0; k < BK; k++) {
            float ra[TM], rb[TN];
            #pragma unroll
            for (int i = 0; i < TM; i++) ra[i] = As[k][tRow * TM + i];
            #pragma unroll
            for (int j = 0; j < TN; j++) rb[j] = Bs[k][tCol * TN + j];
            #pragma unroll
            for (int i = 0; i < TM; i++)
                #pragma unroll
                for (int j = 0; j < TN; j++)
                    acc[i][j] = fmaf(ra[i], rb[j], acc[i][j]);
        }
        __syncthreads();
    }

    #pragma unroll
    for (int i = 0; i < TM; i++) {
        float* Crow = C + (size_t)(by * BM + tRow * TM + i) * N + bx * BN + tCol * TN;
        #pragma unroll
        for (int j = 0; j < TN; j += 4) {
            float4 v = make_float4(acc[i][j], acc[i][j+1], acc[i][j+2], acc[i][j+3]);
            *(float4*)(Crow + j) = v;
        }
    }
}

// ---------------- RoPE (interleaved pairs) ----------------
// x layout: [SEQ, nheads, HDIM]; cos/sin: [SEQ, HDIM/2]
__global__ void rope_kernel(float* __restrict__ x,
                            const float* __restrict__ cosb,
                            const float* __restrict__ sinb,
                            int nheads)
{
    int idx = blockIdx.x * blockDim.x + threadIdx.x;
    int total = SEQ * nheads * (HDIM / 2);
    if (idx >= total) return;
    int f = idx & 31;                      // freq index 0..31
    int h = (idx >> 5) % nheads;
    int s = idx / (32 * nheads);
    float c  = cosb[s * 32 + f];
    float sn = sinb[s * 32 + f];
    size_t base = ((size_t)s * nheads + h) * HDIM + 2 * f;
    float xe = x[base], xo = x[base + 1];
    x[base]     = xe * c - xo * sn;
    x[base + 1] = xe * sn + xo * c;
}

// ---------------- fp32 flash attention (causal, GQA) ----------------
// grid: (qblocks=32, heads=32), 256 threads.
// smem: Qs[64][68], KPs[64][68] (K tile, reused for P), Vs[64][68]
#define FPAD 68
#define FLASH_SMEM (3 * 64 * FPAD * 4)

__global__ __launch_bounds__(256) void flash_kernel(
    const float* __restrict__ Q,   // [SEQ, DIM]
    const float* __restrict__ K,   // [SEQ, KVDIM]
    const float* __restrict__ V,   // [SEQ, KVDIM]
    float* __restrict__ O)         // [SEQ, DIM]
{
    extern __shared__ float sm[];
    float* Qs  = sm;
    float* KPs = sm + 64 * FPAD;
    float* Vs  = sm + 2 * 64 * FPAD;

    const int qb = blockIdx.x;       // query block
    const int h  = blockIdx.y;       // head
    const int hk = h >> 2;           // kv head
    const int tid = threadIdx.x;
    const int ty = tid >> 4;         // 0..15
    const int tx = tid & 15;         // 0..15
    const int r0 = ty * 4;           // row base (query within block)
    const int c0 = tx * 4;           // col base
    const int q0 = qb * 64;

    // load Q tile
    for (int i = tid; i < 64 * 16; i += 256) {
        int r = i >> 4, c4 = (i & 15) * 4;
        *(float4*)(Qs + r * FPAD + c4) =
            *(const float4*)(Q + (size_t)(q0 + r) * DIM + h * HDIM + c4);
    }

    float accO[4][4];
    #pragma unroll
    for (int i = 0; i < 4; i++)
        #pragma unroll
        for (int j = 0; j < 4; j++) accO[i][j] = 0.0f;
    float mrow[4] = {-1e30f, -1e30f, -1e30f, -1e30f};
    float lrow[4] = {0.f, 0.f, 0.f, 0.f};

    const float scale = 0.125f;   // 1/sqrt(64)

    for (int jb = 0; jb <= qb; jb++) {
        __syncthreads();   // previous iter's KPs/Vs reads done
        // load K and V tiles [64 keys, 64 dims]
        for (int i = tid; i < 64 * 16; i += 256) {
            int r = i >> 4, c4 = (i & 15) * 4;
            size_t gro = (size_t)(jb * 64 + r) * KVDIM + hk * HDIM + c4;
            *(float4*)(KPs + r * FPAD + c4) = *(const float4*)(K + gro);
            *(float4*)(Vs  + r * FPAD + c4) = *(const float4*)(V + gro);
        }
        __syncthreads();

        // S = Q @ K^T  (4x4 per thread)
        float s[4][4];
        #pragma unroll
        for (int i = 0; i < 4; i++)
            #pragma unroll
            for (int j = 0; j < 4; j++) s[i][j] = 0.0f;

        #pragma unroll 4
        for (int k4 = 0; k4 < 16; k4++) {
            float4 qv[4], kv[4];
            #pragma unroll
            for (int i = 0; i < 4; i++)
                qv[i] = *(float4*)(Qs + (r0 + i) * FPAD + k4 * 4);
            #pragma unroll
            for (int j = 0; j < 4; j++)
                kv[j] = *(float4*)(KPs + (c0 + j) * FPAD + k4 * 4);
            #pragma unroll
            for (int i = 0; i < 4; i++)
                #pragma unroll
                for (int j = 0; j < 4; j++) {
                    s[i][j] = fmaf(qv[i].x, kv[j].x, s[i][j]);
                    s[i][j] = fmaf(qv[i].y, kv[j].y, s[i][j]);
                    s[i][j] = fmaf(qv[i].z, kv[j].z, s[i][j]);
                    s[i][j] = fmaf(qv[i].w, kv[j].w, s[i][j]);
                }
        }
        #pragma unroll
        for (int i = 0; i < 4; i++)
            #pragma unroll
            for (int j = 0; j < 4; j++) s[i][j] *= scale;

        // causal mask on diagonal block
        if (jb == qb) {
            #pragma unroll
            for (int i = 0; i < 4; i++)
                #pragma unroll
                for (int j = 0; j < 4; j++)
                    if (c0 + j > r0 + i) s[i][j] = -1e30f;
        }

        // online softmax (row groups = 16 lanes sharing ty)
        float alpha[4];
        float p[4][4];
        #pragma unroll
        for (int i = 0; i < 4; i++) {
            float rm = fmaxf(fmaxf(s[i][0], s[i][1]), fmaxf(s[i][2], s[i][3]));
            #pragma unroll
            for (int off = 8; off >= 1; off >>= 1)
                rm = fmaxf(rm, __shfl_xor_sync(0xffffffffu, rm, off, 16));
            float mnew = fmaxf(mrow[i], rm);
            alpha[i] = __expf(mrow[i] - mnew);
            mrow[i] = mnew;
            float rs = 0.0f;
            #pragma unroll
            for (int j = 0; j < 4; j++) {
                p[i][j] = __expf(s[i][j] - mnew);
                rs += p[i][j];
            }
            #pragma unroll
            for (int off = 8; off >= 1; off >>= 1)
                rs += __shfl_xor_sync(0xffffffffu, rs, off, 16);
            lrow[i] = lrow[i] * alpha[i] + rs;
            #pragma unroll
            for (int j = 0; j < 4; j++) accO[i][j] *= alpha[i];
        }

        __syncthreads();  // all S reads of KPs done before overwriting with P
        #pragma unroll
        for (int i = 0; i < 4; i++)
            #pragma unroll
            for (int j = 0; j < 4; j++)
                KPs[(r0 + i) * FPAD + c0 + j] = p[i][j];
        __syncthreads();

        // O += P @ V
        #pragma unroll 4
        for (int k4 = 0; k4 < 16; k4++) {
            float4 pv[4];
            #pragma unroll
            for (int i = 0; i < 4; i++)
                pv[i] = *(float4*)(KPs + (r0 + i) * FPAD + k4 * 4);
            #pragma unroll
            for (int kk = 0; kk < 4; kk++) {
                float4 vv = *(float4*)(Vs + (k4 * 4 + kk) * FPAD + c0);
                #pragma unroll
                for (int i = 0; i < 4; i++) {
                    float pe = (kk == 0) ? pv[i].x : (kk == 1) ? pv[i].y
                             : (kk == 2) ? pv[i].z : pv[i].w;
                    accO[i][0] = fmaf(pe, vv.x, accO[i][0]);
                    accO[i][1] = fmaf(pe, vv.y, accO[i][1]);
                    accO[i][2] = fmaf(pe, vv.z, accO[i][2]);
                    accO[i][3] = fmaf(pe, vv.w, accO[i][3]);
                }
            }
        }
    }

    // normalize + write out: O[(q0+r), h*64 + c]
    #pragma unroll
    for (int i = 0; i < 4; i++) {
        float inv = 1.0f / lrow[i];
        float4 v = make_float4(accO[i][0] * inv, accO[i][1] * inv,
                               accO[i][2] * inv, accO[i][3] * inv);
        *(float4*)(O + (size_t)(q0 + r0 + i) * DIM + h * HDIM + c0) = v;
    }
}

// ---------------- launch ----------------
extern "C" void kernel_launch(void* const* d_in, const int* in_sizes, int n_in,
                              void* d_out, int out_size)
{
    const float* x  = (const float*)d_in[0];
    const float* fc = (const float*)d_in[1];
    const float* fs = (const float*)d_in[2];
    // d_in[3] = mask (unused; causal handled analytically)
    const float* wq = (const float*)d_in[4];
    const float* wk = (const float*)d_in[5];
    const float* wv = (const float*)d_in[6];
    const float* wo = (const float*)d_in[7];
    float* out = (float*)d_out;

    float *dQ, *dK, *dV, *dA;
    cudaGetSymbolAddress((void**)&dQ, g_Q);
    cudaGetSymbolAddress((void**)&dK, g_K);
    cudaGetSymbolAddress((void**)&dV, g_V);
    cudaGetSymbolAddress((void**)&dA, g_A);

    // QKV projections
    sgemm_kernel<<<dim3(DIM / 128, SEQ / 128), 256>>>(SEQ, DIM,   DIM, x, wq, dQ);
    sgemm_kernel<<<dim3(KVDIM / 128, SEQ / 128), 256>>>(SEQ, KVDIM, DIM, x, wk, dK);
    sgemm_kernel<<<dim3(KVDIM / 128, SEQ / 128), 256>>>(SEQ, KVDIM, DIM, x, wv, dV);

    // RoPE
    rope_kernel<<<(SEQ * NHEADS * 32 + 255) / 256, 256>>>(dQ, fc, fs, NHEADS);
    rope_kernel<<<(SEQ * NKV * 32 + 255) / 256, 256>>>(dK, fc, fs, NKV);

    // flash attention
    cudaFuncSetAttribute(flash_kernel, cudaFuncAttributeMaxDynamicSharedMemorySize,
                         FLASH_SMEM);
    flash_kernel<<<dim3(SEQ / 64, NHEADS), 256, FLASH_SMEM>>>(dQ, dK, dV, dA);

    // output projection
    sgemm_kernel<<<dim3(DIM / 128, SEQ / 128), 256>>>(SEQ, DIM, DIM, dA, wo, out);
}

// round 3
// speedup vs baseline: 1.6214x; 1.6214x over previous
#include <cuda_runtime.h>
#include <cuda_bf16.h>
#include <mma.h>
#include <math.h>
#include <stdint.h>

using namespace nvcuda;

// ---------------- problem constants ----------------
#define SEQ      2048
#define DIM      2048
#define NHEADS   32
#define NKV      8
#define HDIM     64
#define KVDIM    (NKV * HDIM)      // 512

// ---------------- scratch (no allocs allowed) ----------------
__device__ float g_Q[(size_t)SEQ * DIM];
__device__ float g_K[(size_t)SEQ * KVDIM];
__device__ float g_V[(size_t)SEQ * KVDIM];
__device__ float g_A[(size_t)SEQ * DIM];

__device__ __nv_bfloat16 g_xh[(size_t)SEQ * DIM], g_xl[(size_t)SEQ * DIM];
__device__ __nv_bfloat16 g_ah[(size_t)SEQ * DIM], g_al[(size_t)SEQ * DIM];
__device__ __nv_bfloat16 g_wqh[(size_t)DIM * DIM], g_wql[(size_t)DIM * DIM];   // [N,K]
__device__ __nv_bfloat16 g_wkh[(size_t)KVDIM * DIM], g_wkl[(size_t)KVDIM * DIM];
__device__ __nv_bfloat16 g_wvh[(size_t)KVDIM * DIM], g_wvl[(size_t)KVDIM * DIM];
__device__ __nv_bfloat16 g_woh[(size_t)DIM * DIM], g_wol[(size_t)DIM * DIM];

// ---------------- helpers ----------------
__device__ __forceinline__ uint32_t smem_u32(const void* p) {
    uint32_t a;
    asm("{ .reg .u64 t; cvta.to.shared.u64 t, %1; cvt.u32.u64 %0, t; }" : "=r"(a) : "l"(p));
    return a;
}
#define CP_ASYNC16(dst, src) \
    asm volatile("cp.async.cg.shared.global [%0], [%1], 16;" :: "r"(dst), "l"(src))
#define CP_COMMIT() asm volatile("cp.async.commit_group;" ::: "memory")
#define CP_WAIT(n)  asm volatile("cp.async.wait_group %0;" :: "n"(n) : "memory")

// ---------------- WMMA bf16 GEMM: C[M,N] = A[M,K] @ Bt[N,K]^T ----------------
// A as hi/lo bf16 [M,K] row-major; B as hi/lo bf16 [N,K].
// C = Ah*Bh + Al*Bh + Ah*Bl (fp32 accum).
#define BM 128
#define BN 128
#define BK 32
#define LDT 40                         // padded leading dim (bf16 elements)
#define TILE_EL (128 * LDT)            // per-tile smem elements
#define STAGE_EL (4 * TILE_EL)         // Ah, Al, Bh, Bl
#define GEMM_SMEM (2 * STAGE_EL * 2)   // bytes (double-buffered) = 81920

__global__ __launch_bounds__(256) void gemm_wmma(
    int M, int N, int K,
    const __nv_bfloat16* __restrict__ Ah, const __nv_bfloat16* __restrict__ Al,
    const __nv_bfloat16* __restrict__ Bh, const __nv_bfloat16* __restrict__ Bl,
    float* __restrict__ C)
{
    extern __shared__ __nv_bfloat16 smb[];
    const int tid = threadIdx.x;
    const int wid = tid >> 5;
    const int wm = wid & 1;        // 0..1 -> 64-row slab
    const int wn = wid >> 1;       // 0..3 -> 32-col slab
    const int m0 = blockIdx.y * BM;
    const int n0 = blockIdx.x * BN;
    const uint32_t sb = smem_u32(smb);

    wmma::fragment<wmma::accumulator, 16, 16, 16, float> acc[4][2];
    #pragma unroll
    for (int i = 0; i < 4; i++)
        #pragma unroll
        for (int j = 0; j < 2; j++) wmma::fill_fragment(acc[i][j], 0.0f);

    const int NC = K / BK;

    // async-load one k-chunk into stage s
    auto load_chunk = [&](int s, int c) {
        #pragma unroll
        for (int it = 0; it < 8; it++) {
            int i = tid + it * 256;       // 0..2047
            int t = i >> 9;               // tile: 0=Ah 1=Al 2=Bh 3=Bl
            int r = (i >> 2) & 127;       // row within tile
            int g = i & 3;                // 16B granule (8 bf16)
            const __nv_bfloat16* gp;
            if      (t == 0) gp = Ah + (size_t)(m0 + r) * K;
            else if (t == 1) gp = Al + (size_t)(m0 + r) * K;
            else if (t == 2) gp = Bh + (size_t)(n0 + r) * K;
            else             gp = Bl + (size_t)(n0 + r) * K;
            gp += c * BK + g * 8;
            uint32_t dst = sb + (uint32_t)(s * STAGE_EL + t * TILE_EL + r * LDT + g * 8) * 2;
            CP_ASYNC16(dst, gp);
        }
        CP_COMMIT();
    };

    load_chunk(0, 0);

    for (int c = 0; c < NC; c++) {
        const int s = c & 1;
        if (c + 1 < NC) { load_chunk(s ^ 1, c + 1); CP_WAIT(1); }
        else            { CP_WAIT(0); }
        __syncthreads();

        const __nv_bfloat16* Ash = smb + s * STAGE_EL;
        const __nv_bfloat16* Asl = Ash + TILE_EL;
        const __nv_bfloat16* Bsh = Ash + 2 * TILE_EL;
        const __nv_bfloat16* Bsl = Ash + 3 * TILE_EL;

        #pragma unroll
        for (int kk = 0; kk < 2; kk++) {
            wmma::fragment<wmma::matrix_a, 16, 16, 16, __nv_bfloat16, wmma::row_major> af[4];
            wmma::fragment<wmma::matrix_b, 16, 16, 16, __nv_bfloat16, wmma::col_major> bfh[2], bfl[2];
            #pragma unroll
            for (int j = 0; j < 2; j++) {
                wmma::load_matrix_sync(bfh[j], Bsh + (wn * 32 + j * 16) * LDT + kk * 16, LDT);
                wmma::load_matrix_sync(bfl[j], Bsl + (wn * 32 + j * 16) * LDT + kk * 16, LDT);
            }
            // combo 1+2: Ah * (Bh, Bl)
            #pragma unroll
            for (int i = 0; i < 4; i++)
                wmma::load_matrix_sync(af[i], Ash + (wm * 64 + i * 16) * LDT + kk * 16, LDT);
            #pragma unroll
            for (int i = 0; i < 4; i++)
                #pragma unroll
                for (int j = 0; j < 2; j++) {
                    wmma::mma_sync(acc[i][j], af[i], bfh[j], acc[i][j]);
                    wmma::mma_sync(acc[i][j], af[i], bfl[j], acc[i][j]);
                }
            // combo 3: Al * Bh
            #pragma unroll
            for (int i = 0; i < 4; i++)
                wmma::load_matrix_sync(af[i], Asl + (wm * 64 + i * 16) * LDT + kk * 16, LDT);
            #pragma unroll
            for (int i = 0; i < 4; i++)
                #pragma unroll
                for (int j = 0; j < 2; j++)
                    wmma::mma_sync(acc[i][j], af[i], bfh[j], acc[i][j]);
        }
        __syncthreads();
    }

    #pragma unroll
    for (int i = 0; i < 4; i++)
        #pragma unroll
        for (int j = 0; j < 2; j++) {
            float* cp = C + (size_t)(m0 + wm * 64 + i * 16) * N + n0 + wn * 32 + j * 16;
            wmma::store_matrix_sync(cp, acc[i][j], N, wmma::mem_row_major);
        }
}

// ---------------- split fp32 -> hi/lo bf16 ----------------
__global__ void split_kernel(const float* __restrict__ in,
                             __nv_bfloat16* __restrict__ hi,
                             __nv_bfloat16* __restrict__ lo, int n)
{
    int i = (blockIdx.x * blockDim.x + threadIdx.x) * 4;
    if (i >= n) return;
    float4 v = *(const float4*)(in + i);
    __nv_bfloat16 h0 = __float2bfloat16(v.x), h1 = __float2bfloat16(v.y);
    __nv_bfloat16 h2 = __float2bfloat16(v.z), h3 = __float2bfloat16(v.w);
    __nv_bfloat16 l0 = __float2bfloat16(v.x - __bfloat162float(h0));
    __nv_bfloat16 l1 = __float2bfloat16(v.y - __bfloat162float(h1));
    __nv_bfloat16 l2 = __float2bfloat16(v.z - __bfloat162float(h2));
    __nv_bfloat16 l3 = __float2bfloat16(v.w - __bfloat162float(h3));
    __nv_bfloat162* hp = (__nv_bfloat162*)(hi + i);
    __nv_bfloat162* lp = (__nv_bfloat162*)(lo + i);
    hp[0] = __nv_bfloat162(h0, h1); hp[1] = __nv_bfloat162(h2, h3);
    lp[0] = __nv_bfloat162(l0, l1); lp[1] = __nv_bfloat162(l2, l3);
}

// ---------------- split + transpose: in [K,N] fp32 -> hi/lo bf16 [N,K] ----------------
__global__ void split_T_kernel(const float* __restrict__ in,
                               __nv_bfloat16* __restrict__ hi,
                               __nv_bfloat16* __restrict__ lo, int K, int N)
{
    __shared__ float t[32][33];
    int k0 = blockIdx.y * 32, n0 = blockIdx.x * 32;
    int tx = threadIdx.x, ty = threadIdx.y;   // 32 x 8
    #pragma unroll
    for (int r = ty; r < 32; r += 8)
        t[r][tx] = in[(size_t)(k0 + r) * N + n0 + tx];
    __syncthreads();
    #pragma unroll
    for (int r = ty; r < 32; r += 8) {
        float v = t[tx][r];
        __nv_bfloat16 h = __float2bfloat16(v);
        __nv_bfloat16 l = __float2bfloat16(v - __bfloat162float(h));
        size_t o = (size_t)(n0 + r) * K + k0 + tx;
        hi[o] = h; lo[o] = l;
    }
}

// ---------------- RoPE ----------------
__global__ void rope_kernel(float* __restrict__ x,
                            const float* __restrict__ cosb,
                            const float* __restrict__ sinb,
                            int nheads)
{
    int idx = blockIdx.x * blockDim.x + threadIdx.x;
    int total = SEQ * nheads * (HDIM / 2);
    if (idx >= total) return;
    int f = idx & 31;
    int h = (idx >> 5) % nheads;
    int s = idx / (32 * nheads);
    float c  = cosb[s * 32 + f];
    float sn = sinb[s * 32 + f];
    size_t base = ((size_t)s * nheads + h) * HDIM + 2 * f;
    float xe = x[base], xo = x[base + 1];
    x[base]     = xe * c - xo * sn;
    x[base + 1] = xe * sn + xo * c;
}

// ---------------- fp32 flash attention (causal, GQA) ----------------
#define FPAD 68
#define FLASH_SMEM (3 * 64 * FPAD * 4)

__global__ __launch_bounds__(256) void flash_kernel(
    const float* __restrict__ Q,
    const float* __restrict__ K,
    const float* __restrict__ V,
    float* __restrict__ O)
{
    extern __shared__ float smf[];
    float* Qs  = smf;
    float* KPs = smf + 64 * FPAD;
    float* Vs  = smf + 2 * 64 * FPAD;

    const int qb = blockIdx.x;
    const int h  = blockIdx.y;
    const int hk = h >> 2;
    const int tid = threadIdx.x;
    const int ty = tid >> 4;
    const int tx = tid & 15;
    const int r0 = ty * 4;
    const int c0 = tx * 4;
    const int q0 = qb * 64;

    for (int i = tid; i < 64 * 16; i += 256) {
        int r = i >> 4, c4 = (i & 15) * 4;
        *(float4*)(Qs + r * FPAD + c4) =
            *(const float4*)(Q + (size_t)(q0 + r) * DIM + h * HDIM + c4);
    }

    float accO[4][4];
    #pragma unroll
    for (int i = 0; i < 4; i++)
        #pragma unroll
        for (int j = 0; j < 4; j++) accO[i][j] = 0.0f;
    float mrow[4] = {-1e30f, -1e30f, -1e30f, -1e30f};
    float lrow[4] = {0.f, 0.f, 0.f, 0.f};
    const float scale = 0.125f;

    for (int jb = 0; jb <= qb; jb++) {
        __syncthreads();
        for (int i = tid; i < 64 * 16; i += 256) {
            int r = i >> 4, c4 = (i & 15) * 4;
            size_t gro = (size_t)(jb * 64 + r) * KVDIM + hk * HDIM + c4;
            *(float4*)(KPs + r * FPAD + c4) = *(const float4*)(K + gro);
            *(float4*)(Vs  + r * FPAD + c4) = *(const float4*)(V + gro);
        }
        __syncthreads();

        float s[4][4];
        #pragma unroll
        for (int i = 0; i < 4; i++)
            #pragma unroll
            for (int j = 0; j < 4; j++) s[i][j] = 0.0f;

        #pragma unroll 4
        for (int k4 = 0; k4 < 16; k4++) {
            float4 qv[4], kv[4];
            #pragma unroll
            for (int i = 0; i < 4; i++)
                qv[i] = *(float4*)(Qs + (r0 + i) * FPAD + k4 * 4);
            #pragma unroll
            for (int j = 0; j < 4; j++)
                kv[j] = *(float4*)(KPs + (c0 + j) * FPAD + k4 * 4);
            #pragma unroll
            for (int i = 0; i < 4; i++)
                #pragma unroll
                for (int j = 0; j < 4; j++) {
                    s[i][j] = fmaf(qv[i].x, kv[j].x, s[i][j]);
                    s[i][j] = fmaf(qv[i].y, kv[j].y, s[i][j]);
                    s[i][j] = fmaf(qv[i].z, kv[j].z, s[i][j]);
                    s[i][j] = fmaf(qv[i].w, kv[j].w, s[i][j]);
                }
        }
        #pragma unroll
        for (int i = 0; i < 4; i++)
            #pragma unroll
            for (int j = 0; j < 4; j++) s[i][j] *= scale;

        if (jb == qb) {
            #pragma unroll
            for (int i = 0; i < 4; i++)
                #pragma unroll
                for (int j = 0; j < 4; j++)
                    if (c0 + j > r0 + i) s[i][j] = -1e30f;
        }

        float alpha[4];
        float p[4][4];
        #pragma unroll
        for (int i = 0; i < 4; i++) {
            float rm = fmaxf(fmaxf(s[i][0], s[i][1]), fmaxf(s[i][2], s[i][3]));
            #pragma unroll
            for (int off = 8; off >= 1; off >>= 1)
                rm = fmaxf(rm, __shfl_xor_sync(0xffffffffu, rm, off, 16));
            float mnew = fmaxf(mrow[i], rm);
            alpha[i] = __expf(mrow[i] - mnew);
            mrow[i] = mnew;
            float rs = 0.0f;
            #pragma unroll
            for (int j = 0; j < 4; j++) {
                p[i][j] = __expf(s[i][j] - mnew);
                rs += p[i][j];
            }
            #pragma unroll
            for (int off = 8; off >= 1; off >>= 1)
                rs += __shfl_xor_sync(0xffffffffu, rs, off, 16);
            lrow[i] = lrow[i] * alpha[i] + rs;
            #pragma unroll
            for (int j = 0; j < 4; j++) accO[i][j] *= alpha[i];
        }

        __syncthreads();
        #pragma unroll
        for (int i = 0; i < 4; i++)
            #pragma unroll
            for (int j = 0; j < 4; j++)
                KPs[(r0 + i) * FPAD + c0 + j] = p[i][j];
        __syncthreads();

        #pragma unroll 4
        for (int k4 = 0; k4 < 16; k4++) {
            float4 pv[4];
            #pragma unroll
            for (int i = 0; i < 4; i++)
                pv[i] = *(float4*)(KPs + (r0 + i) * FPAD + k4 * 4);
            #pragma unroll
            for (int kk = 0; kk < 4; kk++) {
                float4 vv = *(float4*)(Vs + (k4 * 4 + kk) * FPAD + c0);
                #pragma unroll
                for (int i = 0; i < 4; i++) {
                    float pe = (kk == 0) ? pv[i].x : (kk == 1) ? pv[i].y
                             : (kk == 2) ? pv[i].z : pv[i].w;
                    accO[i][0] = fmaf(pe, vv.x, accO[i][0]);
                    accO[i][1] = fmaf(pe, vv.y, accO[i][1]);
                    accO[i][2] = fmaf(pe, vv.z, accO[i][2]);
                    accO[i][3] = fmaf(pe, vv.w, accO[i][3]);
                }
            }
        }
    }

    #pragma unroll
    for (int i = 0; i < 4; i++) {
        float inv = 1.0f / lrow[i];
        float4 v = make_float4(accO[i][0] * inv, accO[i][1] * inv,
                               accO[i][2] * inv, accO[i][3] * inv);
        *(float4*)(O + (size_t)(q0 + r0 + i) * DIM + h * HDIM + c0) = v;
    }
}

// ---------------- launch ----------------
extern "C" void kernel_launch(void* const* d_in, const int* in_sizes, int n_in,
                              void* d_out, int out_size)
{
    const float* x  = (const float*)d_in[0];
    const float* fc = (const float*)d_in[1];
    const float* fs = (const float*)d_in[2];
    const float* wq = (const float*)d_in[4];
    const float* wk = (const float*)d_in[5];
    const float* wv = (const float*)d_in[6];
    const float* wo = (const float*)d_in[7];
    float* out = (float*)d_out;

    float *dQ, *dK, *dV, *dA;
    cudaGetSymbolAddress((void**)&dQ, g_Q);
    cudaGetSymbolAddress((void**)&dK, g_K);
    cudaGetSymbolAddress((void**)&dV, g_V);
    cudaGetSymbolAddress((void**)&dA, g_A);
    __nv_bfloat16 *xh, *xl, *ah, *al, *wqh, *wql, *wkh, *wkl, *wvh, *wvl, *woh, *wol;
    cudaGetSymbolAddress((void**)&xh, g_xh);   cudaGetSymbolAddress((void**)&xl, g_xl);
    cudaGetSymbolAddress((void**)&ah, g_ah);   cudaGetSymbolAddress((void**)&al, g_al);
    cudaGetSymbolAddress((void**)&wqh, g_wqh); cudaGetSymbolAddress((void**)&wql, g_wql);
    cudaGetSymbolAddress((void**)&wkh, g_wkh); cudaGetSymbolAddress((void**)&wkl, g_wkl);
    cudaGetSymbolAddress((void**)&wvh, g_wvh); cudaGetSymbolAddress((void**)&wvl, g_wvl);
    cudaGetSymbolAddress((void**)&woh, g_woh); cudaGetSymbolAddress((void**)&wol, g_wol);

    cudaFuncSetAttribute(gemm_wmma, cudaFuncAttributeMaxDynamicSharedMemorySize, GEMM_SMEM);
    cudaFuncSetAttribute(flash_kernel, cudaFuncAttributeMaxDynamicSharedMemorySize, FLASH_SMEM);

    // splits
    split_kernel<<<(SEQ * DIM / 4 + 255) / 256, 256>>>(x, xh, xl, SEQ * DIM);
    split_T_kernel<<<dim3(DIM / 32, DIM / 32), dim3(32, 8)>>>(wq, wqh, wql, DIM, DIM);
    split_T_kernel<<<dim3(KVDIM / 32, DIM / 32), dim3(32, 8)>>>(wk, wkh, wkl, DIM, KVDIM);
    split_T_kernel<<<dim3(KVDIM / 32, DIM / 32), dim3(32, 8)>>>(wv, wvh, wvl, DIM, KVDIM);
    split_T_kernel<<<dim3(DIM / 32, DIM / 32), dim3(32, 8)>>>(wo, woh, wol, DIM, DIM);

    // projections (HMMA via wmma)
    gemm_wmma<<<dim3(DIM / 128, SEQ / 128), 256, GEMM_SMEM>>>(SEQ, DIM, DIM, xh, xl, wqh, wql, dQ);
    gemm_wmma<<<dim3(KVDIM / 128, SEQ / 128), 256, GEMM_SMEM>>>(SEQ, KVDIM, DIM, xh, xl, wkh, wkl, dK);
    gemm_wmma<<<dim3(KVDIM / 128, SEQ / 128), 256, GEMM_SMEM>>>(SEQ, KVDIM, DIM, xh, xl, wvh, wvl, dV);

    // RoPE
    rope_kernel<<<(SEQ * NHEADS * 32 + 255) / 256, 256>>>(dQ, fc, fs, NHEADS);
    rope_kernel<<<(SEQ * NKV * 32 + 255) / 256, 256>>>(dK, fc, fs, NKV);

    // flash attention (fp32)
    flash_kernel<<<dim3(SEQ / 64, NHEADS), 256, FLASH_SMEM>>>(dQ, dK, dV, dA);

    // output projection
    split_kernel<<<(SEQ * DIM / 4 + 255) / 256, 256>>>(dA, ah, al, SEQ * DIM);
    gemm_wmma<<<dim3(DIM / 128, SEQ / 128), 256, GEMM_SMEM>>>(SEQ, DIM, DIM, ah, al, woh, wol, out);
}

// round 4
// speedup vs baseline: 2.2346x; 1.3782x over previous
#include <cuda_runtime.h>
#include <cuda_bf16.h>
#include <mma.h>
#include <math.h>
#include <stdint.h>

using namespace nvcuda;

// ---------------- problem constants ----------------
#define SEQ      2048
#define DIM      2048
#define NHEADS   32
#define NKV      8
#define HDIM     64
#define KVDIM    (NKV * HDIM)      // 512

// ---------------- scratch (no allocs allowed) ----------------
__device__ float g_Q[(size_t)SEQ * DIM];
__device__ float g_K[(size_t)SEQ * KVDIM];
__device__ float g_V[(size_t)SEQ * KVDIM];

__device__ __nv_bfloat16 g_xh[(size_t)SEQ * DIM], g_xl[(size_t)SEQ * DIM];
__device__ __nv_bfloat16 g_ah[(size_t)SEQ * DIM], g_al[(size_t)SEQ * DIM];
__device__ __nv_bfloat16 g_wqh[(size_t)DIM * DIM], g_wql[(size_t)DIM * DIM];   // [N,K]
__device__ __nv_bfloat16 g_wkh[(size_t)KVDIM * DIM], g_wkl[(size_t)KVDIM * DIM];
__device__ __nv_bfloat16 g_wvh[(size_t)KVDIM * DIM], g_wvl[(size_t)KVDIM * DIM];
__device__ __nv_bfloat16 g_woh[(size_t)DIM * DIM], g_wol[(size_t)DIM * DIM];

// ---------------- helpers ----------------
__device__ __forceinline__ uint32_t smem_u32(const void* p) {
    uint32_t a;
    asm("{ .reg .u64 t; cvta.to.shared.u64 t, %1; cvt.u32.u64 %0, t; }" : "=r"(a) : "l"(p));
    return a;
}
#define CP_ASYNC16(dst, src) \
    asm volatile("cp.async.cg.shared.global [%0], [%1], 16;" :: "r"(dst), "l"(src))
#define CP_COMMIT() asm volatile("cp.async.commit_group;" ::: "memory")
#define CP_WAIT(n)  asm volatile("cp.async.wait_group %0;" :: "n"(n) : "memory")

__device__ __forceinline__ void split2(float x, __nv_bfloat16& h, __nv_bfloat16& l) {
    h = __float2bfloat16(x);
    l = __float2bfloat16(x - __bfloat162float(h));
}

// ---------------- WMMA bf16 GEMM: C[M,N] = A[M,K] @ Bt[N,K]^T ----------------
#define BM 128
#define BN 128
#define BK 32
#define LDT 40
#define TILE_EL (128 * LDT)
#define STAGE_EL (4 * TILE_EL)
#define GEMM_SMEM (2 * STAGE_EL * 2)

__global__ __launch_bounds__(256) void gemm_wmma(
    int M, int N, int K,
    const __nv_bfloat16* __restrict__ Ah, const __nv_bfloat16* __restrict__ Al,
    const __nv_bfloat16* __restrict__ Bh, const __nv_bfloat16* __restrict__ Bl,
    float* __restrict__ C)
{
    extern __shared__ __nv_bfloat16 smb[];
    const int tid = threadIdx.x;
    const int wid = tid >> 5;
    const int wm = wid & 1;
    const int wn = wid >> 1;
    const int m0 = blockIdx.y * BM;
    const int n0 = blockIdx.x * BN;
    const uint32_t sb = smem_u32(smb);

    wmma::fragment<wmma::accumulator, 16, 16, 16, float> acc[4][2];
    #pragma unroll
    for (int i = 0; i < 4; i++)
        #pragma unroll
        for (int j = 0; j < 2; j++) wmma::fill_fragment(acc[i][j], 0.0f);

    const int NC = K / BK;

    auto load_chunk = [&](int s, int c) {
        #pragma unroll
        for (int it = 0; it < 8; it++) {
            int i = tid + it * 256;
            int t = i >> 9;
            int r = (i >> 2) & 127;
            int g = i & 3;
            const __nv_bfloat16* gp;
            if      (t == 0) gp = Ah + (size_t)(m0 + r) * K;
            else if (t == 1) gp = Al + (size_t)(m0 + r) * K;
            else if (t == 2) gp = Bh + (size_t)(n0 + r) * K;
            else             gp = Bl + (size_t)(n0 + r) * K;
            gp += c * BK + g * 8;
            uint32_t dst = sb + (uint32_t)(s * STAGE_EL + t * TILE_EL + r * LDT + g * 8) * 2;
            CP_ASYNC16(dst, gp);
        }
        CP_COMMIT();
    };

    load_chunk(0, 0);

    for (int c = 0; c < NC; c++) {
        const int s = c & 1;
        if (c + 1 < NC) { load_chunk(s ^ 1, c + 1); CP_WAIT(1); }
        else            { CP_WAIT(0); }
        __syncthreads();

        const __nv_bfloat16* Ash = smb + s * STAGE_EL;
        const __nv_bfloat16* Asl = Ash + TILE_EL;
        const __nv_bfloat16* Bsh = Ash + 2 * TILE_EL;
        const __nv_bfloat16* Bsl = Ash + 3 * TILE_EL;

        #pragma unroll
        for (int kk = 0; kk < 2; kk++) {
            wmma::fragment<wmma::matrix_a, 16, 16, 16, __nv_bfloat16, wmma::row_major> af[4];
            wmma::fragment<wmma::matrix_b, 16, 16, 16, __nv_bfloat16, wmma::col_major> bfh[2], bfl[2];
            #pragma unroll
            for (int j = 0; j < 2; j++) {
                wmma::load_matrix_sync(bfh[j], Bsh + (wn * 32 + j * 16) * LDT + kk * 16, LDT);
                wmma::load_matrix_sync(bfl[j], Bsl + (wn * 32 + j * 16) * LDT + kk * 16, LDT);
            }
            #pragma unroll
            for (int i = 0; i < 4; i++)
                wmma::load_matrix_sync(af[i], Ash + (wm * 64 + i * 16) * LDT + kk * 16, LDT);
            #pragma unroll
            for (int i = 0; i < 4; i++)
                #pragma unroll
                for (int j = 0; j < 2; j++) {
                    wmma::mma_sync(acc[i][j], af[i], bfh[j], acc[i][j]);
                    wmma::mma_sync(acc[i][j], af[i], bfl[j], acc[i][j]);
                }
            #pragma unroll
            for (int i = 0; i < 4; i++)
                wmma::load_matrix_sync(af[i], Asl + (wm * 64 + i * 16) * LDT + kk * 16, LDT);
            #pragma unroll
            for (int i = 0; i < 4; i++)
                #pragma unroll
                for (int j = 0; j < 2; j++)
                    wmma::mma_sync(acc[i][j], af[i], bfh[j], acc[i][j]);
        }
        __syncthreads();
    }

    #pragma unroll
    for (int i = 0; i < 4; i++)
        #pragma unroll
        for (int j = 0; j < 2; j++) {
            float* cp = C + (size_t)(m0 + wm * 64 + i * 16) * N + n0 + wn * 32 + j * 16;
            wmma::store_matrix_sync(cp, acc[i][j], N, wmma::mem_row_major);
        }
}

// ---------------- split fp32 -> hi/lo bf16 ----------------
__global__ void split_kernel(const float* __restrict__ in,
                             __nv_bfloat16* __restrict__ hi,
                             __nv_bfloat16* __restrict__ lo, int n)
{
    int i = (blockIdx.x * blockDim.x + threadIdx.x) * 4;
    if (i >= n) return;
    float4 v = *(const float4*)(in + i);
    __nv_bfloat16 h0, h1, h2, h3, l0, l1, l2, l3;
    split2(v.x, h0, l0); split2(v.y, h1, l1);
    split2(v.z, h2, l2); split2(v.w, h3, l3);
    __nv_bfloat162* hp = (__nv_bfloat162*)(hi + i);
    __nv_bfloat162* lp = (__nv_bfloat162*)(lo + i);
    hp[0] = __nv_bfloat162(h0, h1); hp[1] = __nv_bfloat162(h2, h3);
    lp[0] = __nv_bfloat162(l0, l1); lp[1] = __nv_bfloat162(l2, l3);
}

// ---------------- split + transpose ----------------
__global__ void split_T_kernel(const float* __restrict__ in,
                               __nv_bfloat16* __restrict__ hi,
                               __nv_bfloat16* __restrict__ lo, int K, int N)
{
    __shared__ float t[32][33];
    int k0 = blockIdx.y * 32, n0 = blockIdx.x * 32;
    int tx = threadIdx.x, ty = threadIdx.y;
    #pragma unroll
    for (int r = ty; r < 32; r += 8)
        t[r][tx] = in[(size_t)(k0 + r) * N + n0 + tx];
    __syncthreads();
    #pragma unroll
    for (int r = ty; r < 32; r += 8) {
        float v = t[tx][r];
        __nv_bfloat16 h, l;
        split2(v, h, l);
        size_t o = (size_t)(n0 + r) * K + k0 + tx;
        hi[o] = h; lo[o] = l;
    }
}

// ---------------- RoPE ----------------
__global__ void rope_kernel(float* __restrict__ x,
                            const float* __restrict__ cosb,
                            const float* __restrict__ sinb,
                            int nheads)
{
    int idx = blockIdx.x * blockDim.x + threadIdx.x;
    int total = SEQ * nheads * (HDIM / 2);
    if (idx >= total) return;
    int f = idx & 31;
    int h = (idx >> 5) % nheads;
    int s = idx / (32 * nheads);
    float c  = cosb[s * 32 + f];
    float sn = sinb[s * 32 + f];
    size_t base = ((size_t)s * nheads + h) * HDIM + 2 * f;
    float xe = x[base], xo = x[base + 1];
    x[base]     = xe * c - xo * sn;
    x[base + 1] = xe * sn + xo * c;
}

// ---------------- WMMA flash attention (causal, GQA, hi/lo bf16) ----------------
// grid (16, 32), 256 threads. 128 queries x 64-key tiles.
#define LDQ 72     // bf16 leading dim (pad 8)
#define LDSF 68    // fp32 leading dim (pad 4)
#define FLASH_SMEM 181248

__global__ __launch_bounds__(256) void flash_wmma(
    const float* __restrict__ Q,
    const float* __restrict__ K,
    const float* __restrict__ V,
    __nv_bfloat16* __restrict__ OH,
    __nv_bfloat16* __restrict__ OL)
{
    extern __shared__ char smc[];
    __nv_bfloat16* Qh = (__nv_bfloat16*)smc;        // 128*72
    __nv_bfloat16* Ql = Qh + 128 * LDQ;
    __nv_bfloat16* Kh = Ql + 128 * LDQ;             // 64*72
    __nv_bfloat16* Kl = Kh + 64 * LDQ;
    __nv_bfloat16* Vh = Kl + 64 * LDQ;
    __nv_bfloat16* Vl = Vh + 64 * LDQ;
    __nv_bfloat16* Ph = Vl + 64 * LDQ;              // 128*72
    __nv_bfloat16* Pl = Ph + 128 * LDQ;
    float* S    = (float*)(Pl + 128 * LDQ);          // 128*68
    float* Om   = S + 128 * LDSF;                    // 128*68
    float* mrow = Om + 128 * LDSF;                   // 128
    float* lrow = mrow + 128;                        // 128

    const int qb = gridDim.x - 1 - blockIdx.x;       // heavy blocks first
    const int h  = blockIdx.y;
    const int hk = h >> 2;
    const int q0 = qb * 128;
    const int tid = threadIdx.x;
    const int wid = tid >> 5;
    const int wm = wid & 3;      // 32-row slab
    const int wn = wid >> 2;     // 32-col slab

    // load + split Q tile [128 x 64]
    #pragma unroll
    for (int it = 0; it < 8; it++) {
        int idx = tid + it * 256;
        int r = idx >> 4, c4 = (idx & 15) * 4;
        float4 v = *(const float4*)(Q + (size_t)(q0 + r) * DIM + h * HDIM + c4);
        __nv_bfloat16 h0, h1, h2, h3, l0, l1, l2, l3;
        split2(v.x, h0, l0); split2(v.y, h1, l1);
        split2(v.z, h2, l2); split2(v.w, h3, l3);
        __nv_bfloat162* hp = (__nv_bfloat162*)(Qh + r * LDQ + c4);
        __nv_bfloat162* lp = (__nv_bfloat162*)(Ql + r * LDQ + c4);
        hp[0] = __nv_bfloat162(h0, h1); hp[1] = __nv_bfloat162(h2, h3);
        lp[0] = __nv_bfloat162(l0, l1); lp[1] = __nv_bfloat162(l2, l3);
    }
    for (int idx = tid; idx < 128 * LDSF; idx += 256) Om[idx] = 0.0f;
    if (tid < 128) { mrow[tid] = -1e30f; lrow[tid] = 0.0f; }

    const int njb = 2 * qb + 2;
    for (int jb = 0; jb < njb; jb++) {
        __syncthreads();
        // load + split K,V tiles [64 x 64]
        #pragma unroll
        for (int it = 0; it < 8; it++) {
            int idx = tid + it * 256;
            int t = idx >> 10;                // 0=K, 1=V
            int r = (idx >> 4) & 63;
            int c4 = (idx & 15) * 4;
            const float* src = (t ? V : K) + (size_t)(jb * 64 + r) * KVDIM + hk * HDIM + c4;
            float4 v = *(const float4*)src;
            __nv_bfloat16* dh = (t ? Vh : Kh) + r * LDQ + c4;
            __nv_bfloat16* dl = (t ? Vl : Kl) + r * LDQ + c4;
            __nv_bfloat16 h0, h1, h2, h3, l0, l1, l2, l3;
            split2(v.x, h0, l0); split2(v.y, h1, l1);
            split2(v.z, h2, l2); split2(v.w, h3, l3);
            ((__nv_bfloat162*)dh)[0] = __nv_bfloat162(h0, h1);
            ((__nv_bfloat162*)dh)[1] = __nv_bfloat162(h2, h3);
            ((__nv_bfloat162*)dl)[0] = __nv_bfloat162(l0, l1);
            ((__nv_bfloat162*)dl)[1] = __nv_bfloat162(l2, l3);
        }
        __syncthreads();

        // ---- S = Q @ K^T (hi/lo: Qh*Kh + Ql*Kh + Qh*Kl) ----
        {
            wmma::fragment<wmma::accumulator, 16, 16, 16, float> sacc[2][2];
            #pragma unroll
            for (int i = 0; i < 2; i++)
                #pragma unroll
                for (int j = 0; j < 2; j++) wmma::fill_fragment(sacc[i][j], 0.0f);

            #pragma unroll
            for (int pass = 0; pass < 3; pass++) {
                const __nv_bfloat16* Ap = (pass == 1) ? Ql : Qh;
                const __nv_bfloat16* Bp = (pass == 2) ? Kl : Kh;
                #pragma unroll
                for (int k = 0; k < 4; k++) {
                    wmma::fragment<wmma::matrix_a, 16, 16, 16, __nv_bfloat16, wmma::row_major> af[2];
                    wmma::fragment<wmma::matrix_b, 16, 16, 16, __nv_bfloat16, wmma::col_major> bf[2];
                    #pragma unroll
                    for (int i = 0; i < 2; i++)
                        wmma::load_matrix_sync(af[i], Ap + (wm * 32 + i * 16) * LDQ + k * 16, LDQ);
                    #pragma unroll
                    for (int j = 0; j < 2; j++)
                        wmma::load_matrix_sync(bf[j], Bp + (wn * 32 + j * 16) * LDQ + k * 16, LDQ);
                    #pragma unroll
                    for (int i = 0; i < 2; i++)
                        #pragma unroll
                        for (int j = 0; j < 2; j++)
                            wmma::mma_sync(sacc[i][j], af[i], bf[j], sacc[i][j]);
                }
            }
            #pragma unroll
            for (int i = 0; i < 2; i++)
                #pragma unroll
                for (int j = 0; j < 2; j++)
                    wmma::store_matrix_sync(S + (wm * 32 + i * 16) * LDSF + wn * 32 + j * 16,
                                            sacc[i][j], LDSF, wmma::mem_row_major);
        }
        __syncthreads();

        // ---- online softmax: 2 threads per row ----
        {
            const int row  = tid >> 1;
            const int half = tid & 1;
            float* srow = S + row * LDSF + half * 32;
            const int kbase = jb * 64 + half * 32;
            const int qidx  = q0 + row;

            float vmax = -1e30f;
            #pragma unroll
            for (int c = 0; c < 32; c++) {
                float x = (kbase + c <= qidx) ? srow[c] * 0.125f : -1e30f;
                vmax = fmaxf(vmax, x);
            }
            vmax = fmaxf(vmax, __shfl_xor_sync(0xffffffffu, vmax, 1));
            float mold = mrow[row];
            float mnew = fmaxf(mold, vmax);
            float alpha = __expf(mold - mnew);

            float lsum = 0.0f;
            __nv_bfloat16* ph = Ph + row * LDQ + half * 32;
            __nv_bfloat16* pl = Pl + row * LDQ + half * 32;
            #pragma unroll
            for (int c = 0; c < 32; c++) {
                float x = (kbase + c <= qidx) ? srow[c] * 0.125f : -1e30f;
                float p = __expf(x - mnew);
                lsum += p;
                __nv_bfloat16 hh, ll;
                split2(p, hh, ll);
                ph[c] = hh; pl[c] = ll;
            }
            lsum += __shfl_xor_sync(0xffffffffu, lsum, 1);
            if (half == 0) {
                mrow[row] = mnew;
                lrow[row] = lrow[row] * alpha + lsum;
            }
            float* orow = Om + row * LDSF + half * 32;
            #pragma unroll
            for (int c = 0; c < 32; c++) orow[c] *= alpha;
        }
        __syncthreads();

        // ---- O += P @ V (hi/lo: Ph*Vh + Pl*Vh + Ph*Vl) ----
        {
            wmma::fragment<wmma::accumulator, 16, 16, 16, float> pacc[2][2];
            #pragma unroll
            for (int i = 0; i < 2; i++)
                #pragma unroll
                for (int j = 0; j < 2; j++)
                    wmma::load_matrix_sync(pacc[i][j],
                        Om + (wm * 32 + i * 16) * LDSF + wn * 32 + j * 16,
                        LDSF, wmma::mem_row_major);

            #pragma unroll
            for (int pass = 0; pass < 3; pass++) {
                const __nv_bfloat16* Ap = (pass == 1) ? Pl : Ph;
                const __nv_bfloat16* Bp = (pass == 2) ? Vl : Vh;
                #pragma unroll
                for (int k = 0; k < 4; k++) {
                    wmma::fragment<wmma::matrix_a, 16, 16, 16, __nv_bfloat16, wmma::row_major> af[2];
                    wmma::fragment<wmma::matrix_b, 16, 16, 16, __nv_bfloat16, wmma::row_major> bf[2];
                    #pragma unroll
                    for (int i = 0; i < 2; i++)
                        wmma::load_matrix_sync(af[i], Ap + (wm * 32 + i * 16) * LDQ + k * 16, LDQ);
                    #pragma unroll
                    for (int j = 0; j < 2; j++)
                        wmma::load_matrix_sync(bf[j], Bp + (k * 16) * LDQ + wn * 32 + j * 16, LDQ);
                    #pragma unroll
                    for (int i = 0; i < 2; i++)
                        #pragma unroll
                        for (int j = 0; j < 2; j++)
                            wmma::mma_sync(pacc[i][j], af[i], bf[j], pacc[i][j]);
                }
            }
            #pragma unroll
            for (int i = 0; i < 2; i++)
                #pragma unroll
                for (int j = 0; j < 2; j++)
                    wmma::store_matrix_sync(Om + (wm * 32 + i * 16) * LDSF + wn * 32 + j * 16,
                                            pacc[i][j], LDSF, wmma::mem_row_major);
        }
    }
    __syncthreads();

    // epilogue: normalize + write bf16 hi/lo directly (skip separate split pass)
    #pragma unroll
    for (int it = 0; it < 8; it++) {
        int idx = tid + it * 256;
        int r = idx >> 4, c4 = (idx & 15) * 4;
        float4 o = *(float4*)(Om + r * LDSF + c4);
        float inv = 1.0f / lrow[r];
        o.x *= inv; o.y *= inv; o.z *= inv; o.w *= inv;
        __nv_bfloat16 h0, h1, h2, h3, l0, l1, l2, l3;
        split2(o.x, h0, l0); split2(o.y, h1, l1);
        split2(o.z, h2, l2); split2(o.w, h3, l3);
        size_t go = (size_t)(q0 + r) * DIM + h * HDIM + c4;
        ((__nv_bfloat162*)(OH + go))[0] = __nv_bfloat162(h0, h1);
        ((__nv_bfloat162*)(OH + go))[1] = __nv_bfloat162(h2, h3);
        ((__nv_bfloat162*)(OL + go))[0] = __nv_bfloat162(l0, l1);
        ((__nv_bfloat162*)(OL + go))[1] = __nv_bfloat162(l2, l3);
    }
}

// ---------------- launch ----------------
extern "C" void kernel_launch(void* const* d_in, const int* in_sizes, int n_in,
                              void* d_out, int out_size)
{
    const float* x  = (const float*)d_in[0];
    const float* fc = (const float*)d_in[1];
    const float* fs = (const float*)d_in[2];
    const float* wq = (const float*)d_in[4];
    const float* wk = (const float*)d_in[5];
    const float* wv = (const float*)d_in[6];
    const float* wo = (const float*)d_in[7];
    float* out = (float*)d_out;

    float *dQ, *dK, *dV;
    cudaGetSymbolAddress((void**)&dQ, g_Q);
    cudaGetSymbolAddress((void**)&dK, g_K);
    cudaGetSymbolAddress((void**)&dV, g_V);
    __nv_bfloat16 *xh, *xl, *ah, *al, *wqh, *wql, *wkh, *wkl, *wvh, *wvl, *woh, *wol;
    cudaGetSymbolAddress((void**)&xh, g_xh);   cudaGetSymbolAddress((void**)&xl, g_xl);
    cudaGetSymbolAddress((void**)&ah, g_ah);   cudaGetSymbolAddress((void**)&al, g_al);
    cudaGetSymbolAddress((void**)&wqh, g_wqh); cudaGetSymbolAddress((void**)&wql, g_wql);
    cudaGetSymbolAddress((void**)&wkh, g_wkh); cudaGetSymbolAddress((void**)&wkl, g_wkl);
    cudaGetSymbolAddress((void**)&wvh, g_wvh); cudaGetSymbolAddress((void**)&wvl, g_wvl);
    cudaGetSymbolAddress((void**)&woh, g_woh); cudaGetSymbolAddress((void**)&wol, g_wol);

    cudaFuncSetAttribute(gemm_wmma, cudaFuncAttributeMaxDynamicSharedMemorySize, GEMM_SMEM);
    cudaFuncSetAttribute(flash_wmma, cudaFuncAttributeMaxDynamicSharedMemorySize, FLASH_SMEM);

    // splits
    split_kernel<<<(SEQ * DIM / 4 + 255) / 256, 256>>>(x, xh, xl, SEQ * DIM);
    split_T_kernel<<<dim3(DIM / 32, DIM / 32), dim3(32, 8)>>>(wq, wqh, wql, DIM, DIM);
    split_T_kernel<<<dim3(KVDIM / 32, DIM / 32), dim3(32, 8)>>>(wk, wkh, wkl, DIM, KVDIM);
    split_T_kernel<<<dim3(KVDIM / 32, DIM / 32), dim3(32, 8)>>>(wv, wvh, wvl, DIM, KVDIM);
    split_T_kernel<<<dim3(DIM / 32, DIM / 32), dim3(32, 8)>>>(wo, woh, wol, DIM, DIM);

    // projections (HMMA via wmma)
    gemm_wmma<<<dim3(DIM / 128, SEQ / 128), 256, GEMM_SMEM>>>(SEQ, DIM, DIM, xh, xl, wqh, wql, dQ);
    gemm_wmma<<<dim3(KVDIM / 128, SEQ / 128), 256, GEMM_SMEM>>>(SEQ, KVDIM, DIM, xh, xl, wkh, wkl, dK);
    gemm_wmma<<<dim3(KVDIM / 128, SEQ / 128), 256, GEMM_SMEM>>>(SEQ, KVDIM, DIM, xh, xl, wvh, wvl, dV);

    // RoPE
    rope_kernel<<<(SEQ * NHEADS * 32 + 255) / 256, 256>>>(dQ, fc, fs, NHEADS);
    rope_kernel<<<(SEQ * NKV * 32 + 255) / 256, 256>>>(dK, fc, fs, NKV);

    // flash attention (tensor cores, writes bf16 hi/lo directly)
    flash_wmma<<<dim3(SEQ / 128, NHEADS), 256, FLASH_SMEM>>>(dQ, dK, dV, ah, al);

    // output projection
    gemm_wmma<<<dim3(DIM / 128, SEQ / 128), 256, GEMM_SMEM>>>(SEQ, DIM, DIM, ah, al, woh, wol, out);
}

// round 5
// speedup vs baseline: 2.2464x; 1.0053x over previous
#include <cuda_runtime.h>
#include <cuda_bf16.h>
#include <mma.h>
#include <math.h>
#include <stdint.h>

using namespace nvcuda;

// ---------------- problem constants ----------------
#define SEQ      2048
#define DIM      2048
#define NHEADS   32
#define NKV      8
#define HDIM     64
#define KVDIM    (NKV * HDIM)      // 512

// ---------------- scratch (no allocs allowed) ----------------
__device__ float g_Q[(size_t)SEQ * DIM];
__device__ float g_K[(size_t)SEQ * KVDIM];
__device__ float g_V[(size_t)SEQ * KVDIM];

__device__ __nv_bfloat16 g_xh[(size_t)SEQ * DIM], g_xl[(size_t)SEQ * DIM];
__device__ __nv_bfloat16 g_ah[(size_t)SEQ * DIM], g_al[(size_t)SEQ * DIM];
__device__ __nv_bfloat16 g_wqh[(size_t)DIM * DIM], g_wql[(size_t)DIM * DIM];   // [N,K]
__device__ __nv_bfloat16 g_wkh[(size_t)KVDIM * DIM], g_wkl[(size_t)KVDIM * DIM];
__device__ __nv_bfloat16 g_wvh[(size_t)KVDIM * DIM], g_wvl[(size_t)KVDIM * DIM];
__device__ __nv_bfloat16 g_woh[(size_t)DIM * DIM], g_wol[(size_t)DIM * DIM];

// ---------------- helpers ----------------
__device__ __forceinline__ uint32_t smem_u32(const void* p) {
    uint32_t a;
    asm("{ .reg .u64 t; cvta.to.shared.u64 t, %1; cvt.u32.u64 %0, t; }" : "=r"(a) : "l"(p));
    return a;
}
#define CP_ASYNC16(dst, src) \
    asm volatile("cp.async.cg.shared.global [%0], [%1], 16;" :: "r"(dst), "l"(src))
#define CP_COMMIT() asm volatile("cp.async.commit_group;" ::: "memory")
#define CP_WAIT(n)  asm volatile("cp.async.wait_group %0;" :: "n"(n) : "memory")

__device__ __forceinline__ void split2(float x, __nv_bfloat16& h, __nv_bfloat16& l) {
    h = __float2bfloat16(x);
    l = __float2bfloat16(x - __bfloat162float(h));
}

// ---------------- WMMA bf16 GEMM: C[M,N] = A[M,K] @ Bt[N,K]^T ----------------
#define BM 128
#define BN 128
#define BK 32
#define LDT 40
#define TILE_EL (128 * LDT)
#define STAGE_EL (4 * TILE_EL)
#define GEMM_SMEM (2 * STAGE_EL * 2)

__global__ __launch_bounds__(256, 2) void gemm_wmma(
    int M, int N, int K,
    const __nv_bfloat16* __restrict__ Ah, const __nv_bfloat16* __restrict__ Al,
    const __nv_bfloat16* __restrict__ Bh, const __nv_bfloat16* __restrict__ Bl,
    float* __restrict__ C)
{
    extern __shared__ __nv_bfloat16 smb[];
    const int tid = threadIdx.x;
    const int wid = tid >> 5;
    const int wm = wid & 1;
    const int wn = wid >> 1;
    const int m0 = blockIdx.y * BM;
    const int n0 = blockIdx.x * BN;
    const uint32_t sb = smem_u32(smb);

    wmma::fragment<wmma::accumulator, 16, 16, 16, float> acc[4][2];
    #pragma unroll
    for (int i = 0; i < 4; i++)
        #pragma unroll
        for (int j = 0; j < 2; j++) wmma::fill_fragment(acc[i][j], 0.0f);

    const int NC = K / BK;

    auto load_chunk = [&](int s, int c) {
        #pragma unroll
        for (int it = 0; it < 8; it++) {
            int i = tid + it * 256;
            int t = i >> 9;
            int r = (i >> 2) & 127;
            int g = i & 3;
            const __nv_bfloat16* gp;
            if      (t == 0) gp = Ah + (size_t)(m0 + r) * K;
            else if (t == 1) gp = Al + (size_t)(m0 + r) * K;
            else if (t == 2) gp = Bh + (size_t)(n0 + r) * K;
            else             gp = Bl + (size_t)(n0 + r) * K;
            gp += c * BK + g * 8;
            uint32_t dst = sb + (uint32_t)(s * STAGE_EL + t * TILE_EL + r * LDT + g * 8) * 2;
            CP_ASYNC16(dst, gp);
        }
        CP_COMMIT();
    };

    load_chunk(0, 0);

    for (int c = 0; c < NC; c++) {
        const int s = c & 1;
        if (c + 1 < NC) { load_chunk(s ^ 1, c + 1); CP_WAIT(1); }
        else            { CP_WAIT(0); }
        __syncthreads();

        const __nv_bfloat16* Ash = smb + s * STAGE_EL;
        const __nv_bfloat16* Asl = Ash + TILE_EL;
        const __nv_bfloat16* Bsh = Ash + 2 * TILE_EL;
        const __nv_bfloat16* Bsl = Ash + 3 * TILE_EL;

        #pragma unroll
        for (int kk = 0; kk < 2; kk++) {
            wmma::fragment<wmma::matrix_a, 16, 16, 16, __nv_bfloat16, wmma::row_major> af[4];
            wmma::fragment<wmma::matrix_b, 16, 16, 16, __nv_bfloat16, wmma::col_major> bfh[2], bfl[2];
            #pragma unroll
            for (int j = 0; j < 2; j++) {
                wmma::load_matrix_sync(bfh[j], Bsh + (wn * 32 + j * 16) * LDT + kk * 16, LDT);
                wmma::load_matrix_sync(bfl[j], Bsl + (wn * 32 + j * 16) * LDT + kk * 16, LDT);
            }
            #pragma unroll
            for (int i = 0; i < 4; i++)
                wmma::load_matrix_sync(af[i], Ash + (wm * 64 + i * 16) * LDT + kk * 16, LDT);
            #pragma unroll
            for (int i = 0; i < 4; i++)
                #pragma unroll
                for (int j = 0; j < 2; j++) {
                    wmma::mma_sync(acc[i][j], af[i], bfh[j], acc[i][j]);
                    wmma::mma_sync(acc[i][j], af[i], bfl[j], acc[i][j]);
                }
            #pragma unroll
            for (int i = 0; i < 4; i++)
                wmma::load_matrix_sync(af[i], Asl + (wm * 64 + i * 16) * LDT + kk * 16, LDT);
            #pragma unroll
            for (int i = 0; i < 4; i++)
                #pragma unroll
                for (int j = 0; j < 2; j++)
                    wmma::mma_sync(acc[i][j], af[i], bfh[j], acc[i][j]);
        }
        __syncthreads();
    }

    #pragma unroll
    for (int i = 0; i < 4; i++)
        #pragma unroll
        for (int j = 0; j < 2; j++) {
            float* cp = C + (size_t)(m0 + wm * 64 + i * 16) * N + n0 + wn * 32 + j * 16;
            wmma::store_matrix_sync(cp, acc[i][j], N, wmma::mem_row_major);
        }
}

// ---------------- split fp32 -> hi/lo bf16 ----------------
__global__ void split_kernel(const float* __restrict__ in,
                             __nv_bfloat16* __restrict__ hi,
                             __nv_bfloat16* __restrict__ lo, int n)
{
    int i = (blockIdx.x * blockDim.x + threadIdx.x) * 4;
    if (i >= n) return;
    float4 v = *(const float4*)(in + i);
    __nv_bfloat16 h0, h1, h2, h3, l0, l1, l2, l3;
    split2(v.x, h0, l0); split2(v.y, h1, l1);
    split2(v.z, h2, l2); split2(v.w, h3, l3);
    __nv_bfloat162* hp = (__nv_bfloat162*)(hi + i);
    __nv_bfloat162* lp = (__nv_bfloat162*)(lo + i);
    hp[0] = __nv_bfloat162(h0, h1); hp[1] = __nv_bfloat162(h2, h3);
    lp[0] = __nv_bfloat162(l0, l1); lp[1] = __nv_bfloat162(l2, l3);
}

// ---------------- split + transpose ----------------
__global__ void split_T_kernel(const float* __restrict__ in,
                               __nv_bfloat16* __restrict__ hi,
                               __nv_bfloat16* __restrict__ lo, int K, int N)
{
    __shared__ float t[32][33];
    int k0 = blockIdx.y * 32, n0 = blockIdx.x * 32;
    int tx = threadIdx.x, ty = threadIdx.y;
    #pragma unroll
    for (int r = ty; r < 32; r += 8)
        t[r][tx] = in[(size_t)(k0 + r) * N + n0 + tx];
    __syncthreads();
    #pragma unroll
    for (int r = ty; r < 32; r += 8) {
        float v = t[tx][r];
        __nv_bfloat16 h, l;
        split2(v, h, l);
        size_t o = (size_t)(n0 + r) * K + k0 + tx;
        hi[o] = h; lo[o] = l;
    }
}

// ---------------- RoPE ----------------
__global__ void rope_kernel(float* __restrict__ x,
                            const float* __restrict__ cosb,
                            const float* __restrict__ sinb,
                            int nheads)
{
    int idx = blockIdx.x * blockDim.x + threadIdx.x;
    int total = SEQ * nheads * (HDIM / 2);
    if (idx >= total) return;
    int f = idx & 31;
    int h = (idx >> 5) % nheads;
    int s = idx / (32 * nheads);
    float c  = cosb[s * 32 + f];
    float sn = sinb[s * 32 + f];
    size_t base = ((size_t)s * nheads + h) * HDIM + 2 * f;
    float xe = x[base], xo = x[base + 1];
    x[base]     = xe * c - xo * sn;
    x[base + 1] = xe * sn + xo * c;
}

// ---------------- WMMA flash attention (causal, GQA, hi/lo bf16) ----------------
// grid (16, 32), 256 threads. 128 queries x 64-key tiles.
// K/V tile prefetched via cp.async into fp32 staging (overlaps compute).
#define LDQ 72     // bf16 leading dim (pad 8)
#define LDSF 68    // fp32 leading dim (pad 4)
#define FLASH_SMEM (181248 + 32768)

__global__ __launch_bounds__(256) void flash_wmma(
    const float* __restrict__ Q,
    const float* __restrict__ K,
    const float* __restrict__ V,
    __nv_bfloat16* __restrict__ OH,
    __nv_bfloat16* __restrict__ OL)
{
    extern __shared__ char smc[];
    __nv_bfloat16* Qh = (__nv_bfloat16*)smc;        // 128*72
    __nv_bfloat16* Ql = Qh + 128 * LDQ;
    __nv_bfloat16* Kh = Ql + 128 * LDQ;             // 64*72
    __nv_bfloat16* Kl = Kh + 64 * LDQ;
    __nv_bfloat16* Vh = Kl + 64 * LDQ;
    __nv_bfloat16* Vl = Vh + 64 * LDQ;
    __nv_bfloat16* Ph = Vl + 64 * LDQ;              // 128*72
    __nv_bfloat16* Pl = Ph + 128 * LDQ;
    float* S    = (float*)(Pl + 128 * LDQ);          // 128*68
    float* Om   = S + 128 * LDSF;                    // 128*68
    float* mrow = Om + 128 * LDSF;                   // 128
    float* lrow = mrow + 128;                        // 128
    float* stage = lrow + 128;                       // 8192 floats (K then V, 64x64)
    const uint32_t sb_stage = smem_u32(stage);

    const int qb = gridDim.x - 1 - blockIdx.x;       // heavy blocks first
    const int h  = blockIdx.y;
    const int hk = h >> 2;
    const int q0 = qb * 128;
    const int tid = threadIdx.x;
    const int wid = tid >> 5;
    const int wm = wid & 3;      // 32-row slab
    const int wn = wid >> 2;     // 32-col slab

    const int njb = 2 * qb + 2;

    // prefetch K/V tile 0 into staging
    auto stage_load = [&](int jb) {
        #pragma unroll
        for (int it = 0; it < 8; it++) {
            int idx = tid + it * 256;
            int t = idx >> 10;                // 0=K, 1=V
            int r = (idx >> 4) & 63;
            int c4 = (idx & 15) * 4;
            const float* src = (t ? V : K) + (size_t)(jb * 64 + r) * KVDIM + hk * HDIM + c4;
            uint32_t dst = sb_stage + (uint32_t)(t * 4096 + r * 64 + c4) * 4;
            CP_ASYNC16(dst, src);
        }
        CP_COMMIT();
    };
    stage_load(0);

    // load + split Q tile [128 x 64] (overlaps with staging cp.async)
    #pragma unroll
    for (int it = 0; it < 8; it++) {
        int idx = tid + it * 256;
        int r = idx >> 4, c4 = (idx & 15) * 4;
        float4 v = *(const float4*)(Q + (size_t)(q0 + r) * DIM + h * HDIM + c4);
        __nv_bfloat16 h0, h1, h2, h3, l0, l1, l2, l3;
        split2(v.x, h0, l0); split2(v.y, h1, l1);
        split2(v.z, h2, l2); split2(v.w, h3, l3);
        __nv_bfloat162* hp = (__nv_bfloat162*)(Qh + r * LDQ + c4);
        __nv_bfloat162* lp = (__nv_bfloat162*)(Ql + r * LDQ + c4);
        hp[0] = __nv_bfloat162(h0, h1); hp[1] = __nv_bfloat162(h2, h3);
        lp[0] = __nv_bfloat162(l0, l1); lp[1] = __nv_bfloat162(l2, l3);
    }
    for (int idx = tid; idx < 128 * LDSF; idx += 256) Om[idx] = 0.0f;
    if (tid < 128) { mrow[tid] = -1e30f; lrow[tid] = 0.0f; }

    for (int jb = 0; jb < njb; jb++) {
        CP_WAIT(0);
        __syncthreads();     // staging ready; prev iter's MMAs/rescale done

        // split staging -> K/V hi/lo smem
        #pragma unroll
        for (int it = 0; it < 8; it++) {
            int idx = tid + it * 256;
            int t = idx >> 10;
            int r = (idx >> 4) & 63;
            int c4 = (idx & 15) * 4;
            float4 v = *(float4*)(stage + t * 4096 + r * 64 + c4);
            __nv_bfloat16* dh = (t ? Vh : Kh) + r * LDQ + c4;
            __nv_bfloat16* dl = (t ? Vl : Kl) + r * LDQ + c4;
            __nv_bfloat16 h0, h1, h2, h3, l0, l1, l2, l3;
            split2(v.x, h0, l0); split2(v.y, h1, l1);
            split2(v.z, h2, l2); split2(v.w, h3, l3);
            ((__nv_bfloat162*)dh)[0] = __nv_bfloat162(h0, h1);
            ((__nv_bfloat162*)dh)[1] = __nv_bfloat162(h2, h3);
            ((__nv_bfloat162*)dl)[0] = __nv_bfloat162(l0, l1);
            ((__nv_bfloat162*)dl)[1] = __nv_bfloat162(l2, l3);
        }
        __syncthreads();     // splits visible; staging reads complete

        // prefetch next tile (overlaps all compute below)
        if (jb + 1 < njb) stage_load(jb + 1);

        // ---- S = Q @ K^T (hi/lo: Qh*Kh + Ql*Kh + Qh*Kl) ----
        {
            wmma::fragment<wmma::accumulator, 16, 16, 16, float> sacc[2][2];
            #pragma unroll
            for (int i = 0; i < 2; i++)
                #pragma unroll
                for (int j = 0; j < 2; j++) wmma::fill_fragment(sacc[i][j], 0.0f);

            #pragma unroll
            for (int pass = 0; pass < 3; pass++) {
                const __nv_bfloat16* Ap = (pass == 1) ? Ql : Qh;
                const __nv_bfloat16* Bp = (pass == 2) ? Kl : Kh;
                #pragma unroll
                for (int k = 0; k < 4; k++) {
                    wmma::fragment<wmma::matrix_a, 16, 16, 16, __nv_bfloat16, wmma::row_major> af[2];
                    wmma::fragment<wmma::matrix_b, 16, 16, 16, __nv_bfloat16, wmma::col_major> bf[2];
                    #pragma unroll
                    for (int i = 0; i < 2; i++)
                        wmma::load_matrix_sync(af[i], Ap + (wm * 32 + i * 16) * LDQ + k * 16, LDQ);
                    #pragma unroll
                    for (int j = 0; j < 2; j++)
                        wmma::load_matrix_sync(bf[j], Bp + (wn * 32 + j * 16) * LDQ + k * 16, LDQ);
                    #pragma unroll
                    for (int i = 0; i < 2; i++)
                        #pragma unroll
                        for (int j = 0; j < 2; j++)
                            wmma::mma_sync(sacc[i][j], af[i], bf[j], sacc[i][j]);
                }
            }
            #pragma unroll
            for (int i = 0; i < 2; i++)
                #pragma unroll
                for (int j = 0; j < 2; j++)
                    wmma::store_matrix_sync(S + (wm * 32 + i * 16) * LDSF + wn * 32 + j * 16,
                                            sacc[i][j], LDSF, wmma::mem_row_major);
        }
        __syncthreads();

        // ---- online softmax: 2 threads per row ----
        {
            const int row  = tid >> 1;
            const int half = tid & 1;
            float* srow = S + row * LDSF + half * 32;
            const int kbase = jb * 64 + half * 32;
            const int qidx  = q0 + row;

            float vmax = -1e30f;
            #pragma unroll
            for (int c = 0; c < 32; c++) {
                float x = (kbase + c <= qidx) ? srow[c] * 0.125f : -1e30f;
                vmax = fmaxf(vmax, x);
            }
            vmax = fmaxf(vmax, __shfl_xor_sync(0xffffffffu, vmax, 1));
            float mold = mrow[row];
            float mnew = fmaxf(mold, vmax);
            float alpha = __expf(mold - mnew);

            float lsum = 0.0f;
            __nv_bfloat16* ph = Ph + row * LDQ + half * 32;
            __nv_bfloat16* pl = Pl + row * LDQ + half * 32;
            #pragma unroll
            for (int c = 0; c < 32; c++) {
                float x = (kbase + c <= qidx) ? srow[c] * 0.125f : -1e30f;
                float p = __expf(x - mnew);
                lsum += p;
                __nv_bfloat16 hh, ll;
                split2(p, hh, ll);
                ph[c] = hh; pl[c] = ll;
            }
            lsum += __shfl_xor_sync(0xffffffffu, lsum, 1);
            if (half == 0) {
                mrow[row] = mnew;
                lrow[row] = lrow[row] * alpha + lsum;
            }
            if (alpha != 1.0f) {
                float* orow = Om + row * LDSF + half * 32;
                #pragma unroll
                for (int c = 0; c < 32; c++) orow[c] *= alpha;
            }
        }
        __syncthreads();

        // ---- O += P @ V (hi/lo: Ph*Vh + Pl*Vh + Ph*Vl) ----
        {
            wmma::fragment<wmma::accumulator, 16, 16, 16, float> pacc[2][2];
            #pragma unroll
            for (int i = 0; i < 2; i++)
                #pragma unroll
                for (int j = 0; j < 2; j++)
                    wmma::load_matrix_sync(pacc[i][j],
                        Om + (wm * 32 + i * 16) * LDSF + wn * 32 + j * 16,
                        LDSF, wmma::mem_row_major);

            #pragma unroll
            for (int pass = 0; pass < 3; pass++) {
                const __nv_bfloat16* Ap = (pass == 1) ? Pl : Ph;
                const __nv_bfloat16* Bp = (pass == 2) ? Vl : Vh;
                #pragma unroll
                for (int k = 0; k < 4; k++) {
                    wmma::fragment<wmma::matrix_a, 16, 16, 16, __nv_bfloat16, wmma::row_major> af[2];
                    wmma::fragment<wmma::matrix_b, 16, 16, 16, __nv_bfloat16, wmma::row_major> bf[2];
                    #pragma unroll
                    for (int i = 0; i < 2; i++)
                        wmma::load_matrix_sync(af[i], Ap + (wm * 32 + i * 16) * LDQ + k * 16, LDQ);
                    #pragma unroll
                    for (int j = 0; j < 2; j++)
                        wmma::load_matrix_sync(bf[j], Bp + (k * 16) * LDQ + wn * 32 + j * 16, LDQ);
                    #pragma unroll
                    for (int i = 0; i < 2; i++)
                        #pragma unroll
                        for (int j = 0; j < 2; j++)
                            wmma::mma_sync(pacc[i][j], af[i], bf[j], pacc[i][j]);
                }
            }
            #pragma unroll
            for (int i = 0; i < 2; i++)
                #pragma unroll
                for (int j = 0; j < 2; j++)
                    wmma::store_matrix_sync(Om + (wm * 32 + i * 16) * LDSF + wn * 32 + j * 16,
                                            pacc[i][j], LDSF, wmma::mem_row_major);
        }
    }
    __syncthreads();

    // epilogue: normalize + write bf16 hi/lo directly
    #pragma unroll
    for (int it = 0; it < 8; it++) {
        int idx = tid + it * 256;
        int r = idx >> 4, c4 = (idx & 15) * 4;
        float4 o = *(float4*)(Om + r * LDSF + c4);
        float inv = 1.0f / lrow[r];
        o.x *= inv; o.y *= inv; o.z *= inv; o.w *= inv;
        __nv_bfloat16 h0, h1, h2, h3, l0, l1, l2, l3;
        split2(o.x, h0, l0); split2(o.y, h1, l1);
        split2(o.z, h2, l2); split2(o.w, h3, l3);
        size_t go = (size_t)(q0 + r) * DIM + h * HDIM + c4;
        ((__nv_bfloat162*)(OH + go))[0] = __nv_bfloat162(h0, h1);
        ((__nv_bfloat162*)(OH + go))[1] = __nv_bfloat162(h2, h3);
        ((__nv_bfloat162*)(OL + go))[0] = __nv_bfloat162(l0, l1);
        ((__nv_bfloat162*)(OL + go))[1] = __nv_bfloat162(l2, l3);
    }
}

// ---------------- launch ----------------
extern "C" void kernel_launch(void* const* d_in, const int* in_sizes, int n_in,
                              void* d_out, int out_size)
{
    const float* x  = (const float*)d_in[0];
    const float* fc = (const float*)d_in[1];
    const float* fs = (const float*)d_in[2];
    const float* wq = (const float*)d_in[4];
    const float* wk = (const float*)d_in[5];
    const float* wv = (const float*)d_in[6];
    const float* wo = (const float*)d_in[7];
    float* out = (float*)d_out;

    float *dQ, *dK, *dV;
    cudaGetSymbolAddress((void**)&dQ, g_Q);
    cudaGetSymbolAddress((void**)&dK, g_K);
    cudaGetSymbolAddress((void**)&dV, g_V);
    __nv_bfloat16 *xh, *xl, *ah, *al, *wqh, *wql, *wkh, *wkl, *wvh, *wvl, *woh, *wol;
    cudaGetSymbolAddress((void**)&xh, g_xh);   cudaGetSymbolAddress((void**)&xl, g_xl);
    cudaGetSymbolAddress((void**)&ah, g_ah);   cudaGetSymbolAddress((void**)&al, g_al);
    cudaGetSymbolAddress((void**)&wqh, g_wqh); cudaGetSymbolAddress((void**)&wql, g_wql);
    cudaGetSymbolAddress((void**)&wkh, g_wkh); cudaGetSymbolAddress((void**)&wkl, g_wkl);
    cudaGetSymbolAddress((void**)&wvh, g_wvh); cudaGetSymbolAddress((void**)&wvl, g_wvl);
    cudaGetSymbolAddress((void**)&woh, g_woh); cudaGetSymbolAddress((void**)&wol, g_wol);

    cudaFuncSetAttribute(gemm_wmma, cudaFuncAttributeMaxDynamicSharedMemorySize, GEMM_SMEM);
    cudaFuncSetAttribute(flash_wmma, cudaFuncAttributeMaxDynamicSharedMemorySize, FLASH_SMEM);

    // splits
    split_kernel<<<(SEQ * DIM / 4 + 255) / 256, 256>>>(x, xh, xl, SEQ * DIM);
    split_T_kernel<<<dim3(DIM / 32, DIM / 32), dim3(32, 8)>>>(wq, wqh, wql, DIM, DIM);
    split_T_kernel<<<dim3(KVDIM / 32, DIM / 32), dim3(32, 8)>>>(wk, wkh, wkl, DIM, KVDIM);
    split_T_kernel<<<dim3(KVDIM / 32, DIM / 32), dim3(32, 8)>>>(wv, wvh, wvl, DIM, KVDIM);
    split_T_kernel<<<dim3(DIM / 32, DIM / 32), dim3(32, 8)>>>(wo, woh, wol, DIM, DIM);

    // projections (HMMA via wmma)
    gemm_wmma<<<dim3(DIM / 128, SEQ / 128), 256, GEMM_SMEM>>>(SEQ, DIM, DIM, xh, xl, wqh, wql, dQ);
    gemm_wmma<<<dim3(KVDIM / 128, SEQ / 128), 256, GEMM_SMEM>>>(SEQ, KVDIM, DIM, xh, xl, wkh, wkl, dK);
    gemm_wmma<<<dim3(KVDIM / 128, SEQ / 128), 256, GEMM_SMEM>>>(SEQ, KVDIM, DIM, xh, xl, wvh, wvl, dV);

    // RoPE
    rope_kernel<<<(SEQ * NHEADS * 32 + 255) / 256, 256>>>(dQ, fc, fs, NHEADS);
    rope_kernel<<<(SEQ * NKV * 32 + 255) / 256, 256>>>(dK, fc, fs, NKV);

    // flash attention (tensor cores, writes bf16 hi/lo directly)
    flash_wmma<<<dim3(SEQ / 128, NHEADS), 256, FLASH_SMEM>>>(dQ, dK, dV, ah, al);

    // output projection
    gemm_wmma<<<dim3(DIM / 128, SEQ / 128), 256, GEMM_SMEM>>>(SEQ, DIM, DIM, ah, al, woh, wol, out);
}

// round 6
// speedup vs baseline: 2.6165x; 1.1648x over previous
#include <cuda_runtime.h>
#include <cuda_bf16.h>
#include <mma.h>
#include <math.h>
#include <stdint.h>

using namespace nvcuda;

// ---------------- problem constants ----------------
#define SEQ      2048
#define DIM      2048
#define NHEADS   32
#define NKV      8
#define HDIM     64
#define KVDIM    (NKV * HDIM)      // 512
#define QKVD     3072              // fused QKV row stride

// ---------------- scratch (no allocs allowed) ----------------
__device__ float g_QKV[(size_t)SEQ * QKVD];            // 24 MB fused Q|K|V

__device__ __nv_bfloat16 g_xh[(size_t)SEQ * DIM], g_xl[(size_t)SEQ * DIM];
__device__ __nv_bfloat16 g_ah[(size_t)SEQ * DIM], g_al[(size_t)SEQ * DIM];
__device__ __nv_bfloat16 g_wqkvh[(size_t)QKVD * DIM], g_wqkvl[(size_t)QKVD * DIM]; // [3072,2048]
__device__ __nv_bfloat16 g_woh[(size_t)DIM * DIM], g_wol[(size_t)DIM * DIM];

// ---------------- helpers ----------------
__device__ __forceinline__ uint32_t smem_u32(const void* p) {
    uint32_t a;
    asm("{ .reg .u64 t; cvta.to.shared.u64 t, %1; cvt.u32.u64 %0, t; }" : "=r"(a) : "l"(p));
    return a;
}
#define CP_ASYNC16(dst, src) \
    asm volatile("cp.async.cg.shared.global [%0], [%1], 16;" :: "r"(dst), "l"(src))
#define CP_COMMIT() asm volatile("cp.async.commit_group;" ::: "memory")
#define CP_WAIT(n)  asm volatile("cp.async.wait_group %0;" :: "n"(n) : "memory")

__device__ __forceinline__ void split2(float x, __nv_bfloat16& h, __nv_bfloat16& l) {
    h = __float2bfloat16(x);
    l = __float2bfloat16(x - __bfloat162float(h));
}

// ---------------- WMMA bf16 GEMM: C[M,N] = A[M,K] @ Bt[N,K]^T ----------------
#define BM 128
#define BN 128
#define BK 32
#define LDT 40
#define TILE_EL (128 * LDT)
#define STAGE_EL (4 * TILE_EL)
#define GEMM_SMEM (2 * STAGE_EL * 2)

__global__ __launch_bounds__(256, 2) void gemm_wmma(
    int M, int N, int K,
    const __nv_bfloat16* __restrict__ Ah, const __nv_bfloat16* __restrict__ Al,
    const __nv_bfloat16* __restrict__ Bh, const __nv_bfloat16* __restrict__ Bl,
    float* __restrict__ C)
{
    extern __shared__ __nv_bfloat16 smb[];
    const int tid = threadIdx.x;
    const int wid = tid >> 5;
    const int wm = wid & 1;
    const int wn = wid >> 1;
    const int m0 = blockIdx.y * BM;
    const int n0 = blockIdx.x * BN;
    const uint32_t sb = smem_u32(smb);

    wmma::fragment<wmma::accumulator, 16, 16, 16, float> acc[4][2];
    #pragma unroll
    for (int i = 0; i < 4; i++)
        #pragma unroll
        for (int j = 0; j < 2; j++) wmma::fill_fragment(acc[i][j], 0.0f);

    const int NC = K / BK;

    auto load_chunk = [&](int s, int c) {
        #pragma unroll
        for (int it = 0; it < 8; it++) {
            int i = tid + it * 256;
            int t = i >> 9;
            int r = (i >> 2) & 127;
            int g = i & 3;
            const __nv_bfloat16* gp;
            if      (t == 0) gp = Ah + (size_t)(m0 + r) * K;
            else if (t == 1) gp = Al + (size_t)(m0 + r) * K;
            else if (t == 2) gp = Bh + (size_t)(n0 + r) * K;
            else             gp = Bl + (size_t)(n0 + r) * K;
            gp += c * BK + g * 8;
            uint32_t dst = sb + (uint32_t)(s * STAGE_EL + t * TILE_EL + r * LDT + g * 8) * 2;
            CP_ASYNC16(dst, gp);
        }
        CP_COMMIT();
    };

    load_chunk(0, 0);

    for (int c = 0; c < NC; c++) {
        const int s = c & 1;
        if (c + 1 < NC) { load_chunk(s ^ 1, c + 1); CP_WAIT(1); }
        else            { CP_WAIT(0); }
        __syncthreads();

        const __nv_bfloat16* Ash = smb + s * STAGE_EL;
        const __nv_bfloat16* Asl = Ash + TILE_EL;
        const __nv_bfloat16* Bsh = Ash + 2 * TILE_EL;
        const __nv_bfloat16* Bsl = Ash + 3 * TILE_EL;

        #pragma unroll
        for (int kk = 0; kk < 2; kk++) {
            wmma::fragment<wmma::matrix_a, 16, 16, 16, __nv_bfloat16, wmma::row_major> af[4];
            wmma::fragment<wmma::matrix_b, 16, 16, 16, __nv_bfloat16, wmma::col_major> bfh[2], bfl[2];
            #pragma unroll
            for (int j = 0; j < 2; j++) {
                wmma::load_matrix_sync(bfh[j], Bsh + (wn * 32 + j * 16) * LDT + kk * 16, LDT);
                wmma::load_matrix_sync(bfl[j], Bsl + (wn * 32 + j * 16) * LDT + kk * 16, LDT);
            }
            #pragma unroll
            for (int i = 0; i < 4; i++)
                wmma::load_matrix_sync(af[i], Ash + (wm * 64 + i * 16) * LDT + kk * 16, LDT);
            #pragma unroll
            for (int i = 0; i < 4; i++)
                #pragma unroll
                for (int j = 0; j < 2; j++) {
                    wmma::mma_sync(acc[i][j], af[i], bfh[j], acc[i][j]);
                    wmma::mma_sync(acc[i][j], af[i], bfl[j], acc[i][j]);
                }
            #pragma unroll
            for (int i = 0; i < 4; i++)
                wmma::load_matrix_sync(af[i], Asl + (wm * 64 + i * 16) * LDT + kk * 16, LDT);
            #pragma unroll
            for (int i = 0; i < 4; i++)
                #pragma unroll
                for (int j = 0; j < 2; j++)
                    wmma::mma_sync(acc[i][j], af[i], bfh[j], acc[i][j]);
        }
        __syncthreads();
    }

    #pragma unroll
    for (int i = 0; i < 4; i++)
        #pragma unroll
        for (int j = 0; j < 2; j++) {
            float* cp = C + (size_t)(m0 + wm * 64 + i * 16) * N + n0 + wn * 32 + j * 16;
            wmma::store_matrix_sync(cp, acc[i][j], N, wmma::mem_row_major);
        }
}

// ---------------- split fp32 -> hi/lo bf16 ----------------
__global__ void split_kernel(const float* __restrict__ in,
                             __nv_bfloat16* __restrict__ hi,
                             __nv_bfloat16* __restrict__ lo, int n)
{
    int i = (blockIdx.x * blockDim.x + threadIdx.x) * 4;
    if (i >= n) return;
    float4 v = *(const float4*)(in + i);
    __nv_bfloat16 h0, h1, h2, h3, l0, l1, l2, l3;
    split2(v.x, h0, l0); split2(v.y, h1, l1);
    split2(v.z, h2, l2); split2(v.w, h3, l3);
    __nv_bfloat162* hp = (__nv_bfloat162*)(hi + i);
    __nv_bfloat162* lp = (__nv_bfloat162*)(lo + i);
    hp[0] = __nv_bfloat162(h0, h1); hp[1] = __nv_bfloat162(h2, h3);
    lp[0] = __nv_bfloat162(l0, l1); lp[1] = __nv_bfloat162(l2, l3);
}

// ---------------- split + transpose: in [K,N] fp32 -> hi/lo bf16 [N,K] ----------------
__global__ void split_T_kernel(const float* __restrict__ in,
                               __nv_bfloat16* __restrict__ hi,
                               __nv_bfloat16* __restrict__ lo, int K, int N)
{
    __shared__ float t[32][33];
    int k0 = blockIdx.y * 32, n0 = blockIdx.x * 32;
    int tx = threadIdx.x, ty = threadIdx.y;
    #pragma unroll
    for (int r = ty; r < 32; r += 8)
        t[r][tx] = in[(size_t)(k0 + r) * N + n0 + tx];
    __syncthreads();
    #pragma unroll
    for (int r = ty; r < 32; r += 8) {
        float v = t[tx][r];
        __nv_bfloat16 h, l;
        split2(v, h, l);
        size_t o = (size_t)(n0 + r) * K + k0 + tx;
        hi[o] = h; lo[o] = l;
    }
}

// ---------------- fused RoPE over Q heads (0..31) and K heads (32..39) ----------------
__global__ void rope_kernel(float* __restrict__ x,
                            const float* __restrict__ cosb,
                            const float* __restrict__ sinb)
{
    int idx = blockIdx.x * blockDim.x + threadIdx.x;
    const int NH = NHEADS + NKV;   // 40: cols h*64 cover Q then K exactly
    int total = SEQ * NH * (HDIM / 2);
    if (idx >= total) return;
    int f = idx & 31;
    int h = (idx >> 5) % NH;
    int s = idx / (32 * NH);
    float c  = cosb[s * 32 + f];
    float sn = sinb[s * 32 + f];
    size_t base = (size_t)s * QKVD + h * HDIM + 2 * f;
    float xe = x[base], xo = x[base + 1];
    x[base]     = xe * c - xo * sn;
    x[base + 1] = xe * sn + xo * c;
}

// ---------------- WMMA flash attention (causal, GQA, hi/lo bf16, 512 threads) ----------------
// grid (16, 32), 512 threads. 128 queries x 64-key tiles.
#define LDQ 72     // bf16 leading dim (pad 8)
#define LDSF 68    // fp32 leading dim (pad 4)
#define FLASH_SMEM (181248 + 32768)

__global__ __launch_bounds__(512) void flash_wmma(
    const float* __restrict__ QKV,
    __nv_bfloat16* __restrict__ OH,
    __nv_bfloat16* __restrict__ OL)
{
    extern __shared__ char smc[];
    __nv_bfloat16* Qh = (__nv_bfloat16*)smc;        // 128*72
    __nv_bfloat16* Ql = Qh + 128 * LDQ;
    __nv_bfloat16* Kh = Ql + 128 * LDQ;             // 64*72
    __nv_bfloat16* Kl = Kh + 64 * LDQ;
    __nv_bfloat16* Vh = Kl + 64 * LDQ;
    __nv_bfloat16* Vl = Vh + 64 * LDQ;
    __nv_bfloat16* Ph = Vl + 64 * LDQ;              // 128*72
    __nv_bfloat16* Pl = Ph + 128 * LDQ;
    float* S    = (float*)(Pl + 128 * LDQ);          // 128*68
    float* Om   = S + 128 * LDSF;                    // 128*68
    float* mrow = Om + 128 * LDSF;                   // 128
    float* lrow = mrow + 128;                        // 128
    float* stage = lrow + 128;                       // 8192 floats (K then V, 64x64)
    const uint32_t sb_stage = smem_u32(stage);

    const int qb = gridDim.x - 1 - blockIdx.x;       // heavy blocks first
    const int h  = blockIdx.y;
    const int hk = h >> 2;
    const int q0 = qb * 128;
    const int tid = threadIdx.x;
    const int wid = tid >> 5;
    const int wm = wid & 3;      // 32-row slab
    const int wn = wid >> 2;     // 16-col slab (0..3)

    const float* Qg = QKV + h * HDIM;
    const float* Kg = QKV + 2048 + hk * HDIM;
    const float* Vg = QKV + 2560 + hk * HDIM;

    const int njb = 2 * qb + 2;

    auto stage_load = [&](int jb) {
        #pragma unroll
        for (int it = 0; it < 4; it++) {
            int idx = tid + it * 512;
            int t = idx >> 10;                // 0=K, 1=V
            int r = (idx >> 4) & 63;
            int c4 = (idx & 15) * 4;
            const float* src = (t ? Vg : Kg) + (size_t)(jb * 64 + r) * QKVD + c4;
            uint32_t dst = sb_stage + (uint32_t)(t * 4096 + r * 64 + c4) * 4;
            CP_ASYNC16(dst, src);
        }
        CP_COMMIT();
    };
    stage_load(0);

    // load + split Q tile [128 x 64]
    #pragma unroll
    for (int it = 0; it < 4; it++) {
        int idx = tid + it * 512;
        int r = idx >> 4, c4 = (idx & 15) * 4;
        float4 v = *(const float4*)(Qg + (size_t)(q0 + r) * QKVD + c4);
        __nv_bfloat16 h0, h1, h2, h3, l0, l1, l2, l3;
        split2(v.x, h0, l0); split2(v.y, h1, l1);
        split2(v.z, h2, l2); split2(v.w, h3, l3);
        __nv_bfloat162* hp = (__nv_bfloat162*)(Qh + r * LDQ + c4);
        __nv_bfloat162* lp = (__nv_bfloat162*)(Ql + r * LDQ + c4);
        hp[0] = __nv_bfloat162(h0, h1); hp[1] = __nv_bfloat162(h2, h3);
        lp[0] = __nv_bfloat162(l0, l1); lp[1] = __nv_bfloat162(l2, l3);
    }
    for (int idx = tid; idx < 128 * LDSF; idx += 512) Om[idx] = 0.0f;
    if (tid < 128) { mrow[tid] = -1e30f; lrow[tid] = 0.0f; }

    for (int jb = 0; jb < njb; jb++) {
        CP_WAIT(0);
        __syncthreads();

        // split staging -> K/V hi/lo smem
        #pragma unroll
        for (int it = 0; it < 4; it++) {
            int idx = tid + it * 512;
            int t = idx >> 10;
            int r = (idx >> 4) & 63;
            int c4 = (idx & 15) * 4;
            float4 v = *(float4*)(stage + t * 4096 + r * 64 + c4);
            __nv_bfloat16* dh = (t ? Vh : Kh) + r * LDQ + c4;
            __nv_bfloat16* dl = (t ? Vl : Kl) + r * LDQ + c4;
            __nv_bfloat16 h0, h1, h2, h3, l0, l1, l2, l3;
            split2(v.x, h0, l0); split2(v.y, h1, l1);
            split2(v.z, h2, l2); split2(v.w, h3, l3);
            ((__nv_bfloat162*)dh)[0] = __nv_bfloat162(h0, h1);
            ((__nv_bfloat162*)dh)[1] = __nv_bfloat162(h2, h3);
            ((__nv_bfloat162*)dl)[0] = __nv_bfloat162(l0, l1);
            ((__nv_bfloat162*)dl)[1] = __nv_bfloat162(l2, l3);
        }
        __syncthreads();

        if (jb + 1 < njb) stage_load(jb + 1);

        // ---- S = Q @ K^T (hi/lo), 16 warps: warp tile 32q x 16k ----
        {
            wmma::fragment<wmma::accumulator, 16, 16, 16, float> sacc[2];
            #pragma unroll
            for (int i = 0; i < 2; i++) wmma::fill_fragment(sacc[i], 0.0f);

            #pragma unroll
            for (int pass = 0; pass < 3; pass++) {
                const __nv_bfloat16* Ap = (pass == 1) ? Ql : Qh;
                const __nv_bfloat16* Bp = (pass == 2) ? Kl : Kh;
                #pragma unroll
                for (int k = 0; k < 4; k++) {
                    wmma::fragment<wmma::matrix_a, 16, 16, 16, __nv_bfloat16, wmma::row_major> af[2];
                    wmma::fragment<wmma::matrix_b, 16, 16, 16, __nv_bfloat16, wmma::col_major> bf;
                    wmma::load_matrix_sync(bf, Bp + (wn * 16) * LDQ + k * 16, LDQ);
                    #pragma unroll
                    for (int i = 0; i < 2; i++)
                        wmma::load_matrix_sync(af[i], Ap + (wm * 32 + i * 16) * LDQ + k * 16, LDQ);
                    #pragma unroll
                    for (int i = 0; i < 2; i++)
                        wmma::mma_sync(sacc[i], af[i], bf, sacc[i]);
                }
            }
            #pragma unroll
            for (int i = 0; i < 2; i++)
                wmma::store_matrix_sync(S + (wm * 32 + i * 16) * LDSF + wn * 16,
                                        sacc[i], LDSF, wmma::mem_row_major);
        }
        __syncthreads();

        // ---- online softmax: 4 threads per row, 16 cols each ----
        {
            const int row  = tid >> 2;
            const int quad = tid & 3;
            float* srow = S + row * LDSF + quad * 16;
            const int kbase = jb * 64 + quad * 16;
            const int qidx  = q0 + row;

            float vmax = -1e30f;
            #pragma unroll
            for (int c = 0; c < 16; c++) {
                float x = (kbase + c <= qidx) ? srow[c] * 0.125f : -1e30f;
                vmax = fmaxf(vmax, x);
            }
            vmax = fmaxf(vmax, __shfl_xor_sync(0xffffffffu, vmax, 1, 4));
            vmax = fmaxf(vmax, __shfl_xor_sync(0xffffffffu, vmax, 2, 4));
            float mold = mrow[row];
            float mnew = fmaxf(mold, vmax);
            float alpha = __expf(mold - mnew);

            float lsum = 0.0f;
            __nv_bfloat16* ph = Ph + row * LDQ + quad * 16;
            __nv_bfloat16* pl = Pl + row * LDQ + quad * 16;
            #pragma unroll
            for (int c = 0; c < 16; c++) {
                float x = (kbase + c <= qidx) ? srow[c] * 0.125f : -1e30f;
                float p = __expf(x - mnew);
                lsum += p;
                __nv_bfloat16 hh, ll;
                split2(p, hh, ll);
                ph[c] = hh; pl[c] = ll;
            }
            lsum += __shfl_xor_sync(0xffffffffu, lsum, 1, 4);
            lsum += __shfl_xor_sync(0xffffffffu, lsum, 2, 4);
            if (quad == 0) {
                mrow[row] = mnew;
                lrow[row] = lrow[row] * alpha + lsum;
            }
            if (alpha != 1.0f) {
                float* orow = Om + row * LDSF + quad * 16;
                #pragma unroll
                for (int c = 0; c < 16; c++) orow[c] *= alpha;
            }
        }
        __syncthreads();

        // ---- O += P @ V (hi/lo), warp tile 32q x 16d ----
        {
            wmma::fragment<wmma::accumulator, 16, 16, 16, float> pacc[2];
            #pragma unroll
            for (int i = 0; i < 2; i++)
                wmma::load_matrix_sync(pacc[i],
                    Om + (wm * 32 + i * 16) * LDSF + wn * 16,
                    LDSF, wmma::mem_row_major);

            #pragma unroll
            for (int pass = 0; pass < 3; pass++) {
                const __nv_bfloat16* Ap = (pass == 1) ? Pl : Ph;
                const __nv_bfloat16* Bp = (pass == 2) ? Vl : Vh;
                #pragma unroll
                for (int k = 0; k < 4; k++) {
                    wmma::fragment<wmma::matrix_a, 16, 16, 16, __nv_bfloat16, wmma::row_major> af[2];
                    wmma::fragment<wmma::matrix_b, 16, 16, 16, __nv_bfloat16, wmma::row_major> bf;
                    wmma::load_matrix_sync(bf, Bp + (k * 16) * LDQ + wn * 16, LDQ);
                    #pragma unroll
                    for (int i = 0; i < 2; i++)
                        wmma::load_matrix_sync(af[i], Ap + (wm * 32 + i * 16) * LDQ + k * 16, LDQ);
                    #pragma unroll
                    for (int i = 0; i < 2; i++)
                        wmma::mma_sync(pacc[i], af[i], bf, pacc[i]);
                }
            }
            #pragma unroll
            for (int i = 0; i < 2; i++)
                wmma::store_matrix_sync(Om + (wm * 32 + i * 16) * LDSF + wn * 16,
                                        pacc[i], LDSF, wmma::mem_row_major);
        }
    }
    __syncthreads();

    // epilogue: normalize + write bf16 hi/lo directly
    #pragma unroll
    for (int it = 0; it < 4; it++) {
        int idx = tid + it * 512;
        int r = idx >> 4, c4 = (idx & 15) * 4;
        float4 o = *(float4*)(Om + r * LDSF + c4);
        float inv = 1.0f / lrow[r];
        o.x *= inv; o.y *= inv; o.z *= inv; o.w *= inv;
        __nv_bfloat16 h0, h1, h2, h3, l0, l1, l2, l3;
        split2(o.x, h0, l0); split2(o.y, h1, l1);
        split2(o.z, h2, l2); split2(o.w, h3, l3);
        size_t go = (size_t)(q0 + r) * DIM + h * HDIM + c4;
        ((__nv_bfloat162*)(OH + go))[0] = __nv_bfloat162(h0, h1);
        ((__nv_bfloat162*)(OH + go))[1] = __nv_bfloat162(h2, h3);
        ((__nv_bfloat162*)(OL + go))[0] = __nv_bfloat162(l0, l1);
        ((__nv_bfloat162*)(OL + go))[1] = __nv_bfloat162(l2, l3);
    }
}

// ---------------- launch ----------------
extern "C" void kernel_launch(void* const* d_in, const int* in_sizes, int n_in,
                              void* d_out, int out_size)
{
    const float* x  = (const float*)d_in[0];
    const float* fc = (const float*)d_in[1];
    const float* fs = (const float*)d_in[2];
    const float* wq = (const float*)d_in[4];
    const float* wk = (const float*)d_in[5];
    const float* wv = (const float*)d_in[6];
    const float* wo = (const float*)d_in[7];
    float* out = (float*)d_out;

    float *dQKV;
    cudaGetSymbolAddress((void**)&dQKV, g_QKV);
    __nv_bfloat16 *xh, *xl, *ah, *al, *wqkvh, *wqkvl, *woh, *wol;
    cudaGetSymbolAddress((void**)&xh, g_xh);       cudaGetSymbolAddress((void**)&xl, g_xl);
    cudaGetSymbolAddress((void**)&ah, g_ah);       cudaGetSymbolAddress((void**)&al, g_al);
    cudaGetSymbolAddress((void**)&wqkvh, g_wqkvh); cudaGetSymbolAddress((void**)&wqkvl, g_wqkvl);
    cudaGetSymbolAddress((void**)&woh, g_woh);     cudaGetSymbolAddress((void**)&wol, g_wol);

    cudaFuncSetAttribute(gemm_wmma, cudaFuncAttributeMaxDynamicSharedMemorySize, GEMM_SMEM);
    cudaFuncSetAttribute(flash_wmma, cudaFuncAttributeMaxDynamicSharedMemorySize, FLASH_SMEM);

    // splits (wq/wk/wv transposed into one concatenated [3072, 2048] buffer)
    split_kernel<<<(SEQ * DIM / 4 + 255) / 256, 256>>>(x, xh, xl, SEQ * DIM);
    split_T_kernel<<<dim3(DIM / 32, DIM / 32), dim3(32, 8)>>>(wq, wqkvh, wqkvl, DIM, DIM);
    split_T_kernel<<<dim3(KVDIM / 32, DIM / 32), dim3(32, 8)>>>(
        wk, wqkvh + (size_t)2048 * DIM, wqkvl + (size_t)2048 * DIM, DIM, KVDIM);
    split_T_kernel<<<dim3(KVDIM / 32, DIM / 32), dim3(32, 8)>>>(
        wv, wqkvh + (size_t)2560 * DIM, wqkvl + (size_t)2560 * DIM, DIM, KVDIM);
    split_T_kernel<<<dim3(DIM / 32, DIM / 32), dim3(32, 8)>>>(wo, woh, wol, DIM, DIM);

    // fused QKV projection (one GEMM, N=3072)
    gemm_wmma<<<dim3(QKVD / 128, SEQ / 128), 256, GEMM_SMEM>>>(
        SEQ, QKVD, DIM, xh, xl, wqkvh, wqkvl, dQKV);

    // fused RoPE over Q heads 0..31 and K heads 32..39
    rope_kernel<<<(SEQ * (NHEADS + NKV) * 32 + 255) / 256, 256>>>(dQKV, fc, fs);

    // flash attention (512 threads/CTA, writes bf16 hi/lo directly)
    flash_wmma<<<dim3(SEQ / 128, NHEADS), 512, FLASH_SMEM>>>(dQKV, ah, al);

    // output projection
    gemm_wmma<<<dim3(DIM / 128, SEQ / 128), 256, GEMM_SMEM>>>(SEQ, DIM, DIM, ah, al, woh, wol, out);
}